// round 13
// baseline (speedup 1.0000x reference)
#include <cuda_runtime.h>
#include <cuda_bf16.h>
#include <cuda_fp16.h>
#include <math.h>
#include <stdint.h>

#define C_NB 2
#define C_NL 48
#define C_NN 3000
#define C_ND 128
#define C_NLOUT 24
#define C_BN (C_NB*C_NN)
#define C_ROWS (C_BN*C_NL)
#define C_BL (C_NB*C_NL)
#define KPAD 3008
#define MPAD 3072
#define NCOL (C_BL*C_ND)   // 12288

// ---------------- device-global scratch (aliased) ----------------
__device__ float g_mean[C_BN];
__device__ float g_enc [C_ROWS*C_ND];
__device__ float g_q   [C_ROWS*C_ND];          // fp16 q -> later fp32 res
__device__ float g_kk  [C_ROWS*C_ND];          // fp16 kk
__device__ float g_v   [C_ROWS*C_ND];          // fp16 v
__device__ float g_ff  [C_ROWS*512];           // also: g_agg
__device__ float g_pe  [C_NN*C_ND];
__device__ float g_pe2 [C_NN*C_ND];
__device__ float g_pw  [(size_t)C_NN*C_ND*C_ND];
__device__ float g_gmu [C_BL*4];
__device__ float g_grs [C_BL*4];
__device__ __nv_bfloat16 g_a2 [(size_t)MPAD*KPAD];     // fp16 bits (adj*1024)
__device__ __nv_bfloat16 g_b2 [(size_t)C_ROWS*1536];   // FF1 packed out OR fp16 nf^T
__device__ __nv_bfloat16 g_ap [(size_t)C_ROWS*384];    // LN outs / att0 / packed pe2
__device__ __nv_bfloat16 g_bp [(size_t)16384*384];     // packed weights

__device__ __forceinline__ float geluf(float x){
    return 0.5f*x*(1.0f+erff(x*0.70710678118654752f));
}
__device__ __forceinline__ uint32_t smem_u32(const void* p){
    uint32_t a;
    asm("{ .reg .u64 t; cvta.to.shared.u64 t, %1; cvt.u32.u64 %0, t; }" : "=r"(a) : "l"(p));
    return a;
}
__device__ __forceinline__ void split_bf16(float v, __nv_bfloat16& h, __nv_bfloat16& lo){
    h = __float2bfloat16(v);
    lo = __float2bfloat16(v - __bfloat162float(h));
}
#define CP_ASYNC16(dst, src) asm volatile("cp.async.cg.shared.global [%0], [%1], 16;" :: "r"(dst), "l"(src))
#define CP_COMMIT() asm volatile("cp.async.commit_group;" ::: "memory")
#define CP_WAIT(n)  asm volatile("cp.async.wait_group %0;" :: "n"(n) : "memory")
#define LDSM4(r0,r1,r2,r3,addr) \
    asm volatile("ldmatrix.sync.aligned.m8n8.x4.shared.b16 {%0,%1,%2,%3}, [%4];" \
        : "=r"(r0),"=r"(r1),"=r"(r2),"=r"(r3) : "r"(addr))
#define LDSM4T(r0,r1,r2,r3,addr) \
    asm volatile("ldmatrix.sync.aligned.m8n8.x4.trans.shared.b16 {%0,%1,%2,%3}, [%4];" \
        : "=r"(r0),"=r"(r1),"=r"(r2),"=r"(r3) : "r"(addr))
#define MMA_BF16(d, a, b) asm volatile( \
    "mma.sync.aligned.m16n8k16.row.col.f32.bf16.bf16.f32 " \
    "{%0,%1,%2,%3}, {%4,%5,%6,%7}, {%8,%9}, {%0,%1,%2,%3};" \
    : "+f"((d)[0]),"+f"((d)[1]),"+f"((d)[2]),"+f"((d)[3]) \
    : "r"((a)[0]),"r"((a)[1]),"r"((a)[2]),"r"((a)[3]), "r"((b)[0]),"r"((b)[1]))
#define MMA_F16(d, a, b) asm volatile( \
    "mma.sync.aligned.m16n8k16.row.col.f32.f16.f16.f32 " \
    "{%0,%1,%2,%3}, {%4,%5,%6,%7}, {%8,%9}, {%0,%1,%2,%3};" \
    : "+f"((d)[0]),"+f"((d)[1]),"+f"((d)[2]),"+f"((d)[3]) \
    : "r"((a)[0]),"r"((a)[1]),"r"((a)[2]),"r"((a)[3]), "r"((b)[0]),"r"((b)[1]))

// ---------------- K1: mean + circular conv1d embedding ----------------
__global__ __launch_bounds__(128) void k_embed(const float* __restrict__ x_enc,
                                               const float* __restrict__ conv_w)
{
    int bn = blockIdx.x, b = bn / C_NN, n = bn % C_NN, t = threadIdx.x;
    __shared__ float red[128];
    __shared__ float xs[C_NL+2];
    float v = 0.f;
    if (t < C_NL) v = x_enc[(size_t)(b*C_NL + t)*C_NN + n];
    red[t] = v; __syncthreads();
    #pragma unroll
    for (int s = 64; s > 0; s >>= 1) { if (t < s) red[t] += red[t+s]; __syncthreads(); }
    float mean = red[0] * (1.f/C_NL);
    if (t == 0) g_mean[bn] = mean;
    if (t < C_NL) xs[t+1] = v - mean;
    __syncthreads();
    if (t == 0) { xs[0] = xs[C_NL]; xs[C_NL+1] = xs[1]; }
    __syncthreads();
    float w0 = conv_w[t*3], w1 = conv_w[t*3+1], w2 = conv_w[t*3+2];
    float* out = g_enc + (size_t)bn*C_NL*C_ND;
    #pragma unroll 4
    for (int l = 0; l < C_NL; l++)
        out[l*C_ND + t] = w0*xs[l] + w1*xs[l+1] + w2*xs[l+2];
}

// ---------------- pe projection ----------------
__global__ __launch_bounds__(256) void k_pe(const float* __restrict__ pe_raw,
    const float* __restrict__ pos_w, const float* __restrict__ pos_b)
{
    int idx = blockIdx.x*256 + threadIdx.x;
    if (idx >= C_NN*C_ND) return;
    int n = idx >> 7, d = idx & 127;
    g_pe[idx] = pe_raw[n]*pos_w[d*3] + pe_raw[C_NN+n]*pos_w[d*3+1]
              + pe_raw[2*C_NN+n]*pos_w[d*3+2] + pos_b[d];
}

// ---------------- LayerNorm -> fp16 row ----------------
__global__ __launch_bounds__(256) void k_ln_h(const float* __restrict__ in,
    const float* __restrict__ ga, const float* __restrict__ be,
    __half* __restrict__ outp)
{
    int row = blockIdx.x*8 + (threadIdx.x>>5), lane = threadIdx.x & 31;
    float4 x = *(const float4*)(in + (size_t)row*C_ND + lane*4);
    float s = x.x+x.y+x.z+x.w;
    #pragma unroll
    for (int o=16;o;o>>=1) s += __shfl_xor_sync(~0u, s, o);
    float mean = s*(1.f/128.f);
    float dx=x.x-mean, dy=x.y-mean, dz=x.z-mean, dw=x.w-mean;
    float sq = dx*dx+dy*dy+dz*dz+dw*dw;
    #pragma unroll
    for (int o=16;o;o>>=1) sq += __shfl_xor_sync(~0u, sq, o);
    float rstd = rsqrtf(sq*(1.f/128.f) + 1e-5f);
    float4 g = *(const float4*)(ga + lane*4), bb = *(const float4*)(be + lane*4);
    __half* p = outp + (size_t)row*C_ND + lane*4;
    *(__half2*)(p)   = __floats2half2_rn(dx*rstd*g.x+bb.x, dy*rstd*g.y+bb.y);
    *(__half2*)(p+2) = __floats2half2_rn(dz*rstd*g.z+bb.z, dw*rstd*g.w+bb.w);
}

// ---------------- LayerNorm -> packed bf16 [h|lo|h] ----------------
__global__ __launch_bounds__(256) void k_ln_pack(const float* __restrict__ in,
    const float* __restrict__ ga, const float* __restrict__ be,
    __nv_bfloat16* __restrict__ outp)
{
    int row = blockIdx.x*8 + (threadIdx.x>>5), lane = threadIdx.x & 31;
    float4 x = *(const float4*)(in + (size_t)row*C_ND + lane*4);
    float s = x.x+x.y+x.z+x.w;
    #pragma unroll
    for (int o=16;o;o>>=1) s += __shfl_xor_sync(~0u, s, o);
    float mean = s*(1.f/128.f);
    float dx=x.x-mean, dy=x.y-mean, dz=x.z-mean, dw=x.w-mean;
    float sq = dx*dx+dy*dy+dz*dz+dw*dw;
    #pragma unroll
    for (int o=16;o;o>>=1) sq += __shfl_xor_sync(~0u, sq, o);
    float rstd = rsqrtf(sq*(1.f/128.f) + 1e-5f);
    float4 g = *(const float4*)(ga + lane*4), bb = *(const float4*)(be + lane*4);
    float vv[4] = { dx*rstd*g.x+bb.x, dy*rstd*g.y+bb.y, dz*rstd*g.z+bb.z, dw*rstd*g.w+bb.w };
    __nv_bfloat16 h[4], lo[4];
    #pragma unroll
    for (int i=0;i<4;i++) split_bf16(vv[i], h[i], lo[i]);
    __nv_bfloat16* p = outp + (size_t)row*384 + lane*4;
    *(__nv_bfloat162*)(p)     = __nv_bfloat162{h[0],h[1]};
    *(__nv_bfloat162*)(p+2)   = __nv_bfloat162{h[2],h[3]};
    *(__nv_bfloat162*)(p+128) = __nv_bfloat162{lo[0],lo[1]};
    *(__nv_bfloat162*)(p+130) = __nv_bfloat162{lo[2],lo[3]};
    *(__nv_bfloat162*)(p+256) = __nv_bfloat162{h[0],h[1]};
    *(__nv_bfloat162*)(p+258) = __nv_bfloat162{h[2],h[3]};
}

// ---------------- tiled fp32 SGEMM (pe2 only) ----------------
#define TBK 16
#define SP 132
__global__ __launch_bounds__(256) void sgemm_nn(
    const float* __restrict__ A, const float* __restrict__ Bm,
    float* __restrict__ C, int M, int N, int K)
{
    __shared__ float As[TBK*SP];
    __shared__ float Bs[TBK*SP];
    const int tid = threadIdx.x, ty = tid>>4, tx = tid&15;
    const int rowBase = blockIdx.x*128, colBase = blockIdx.y*128;
    float acc[8][8];
    #pragma unroll
    for (int i=0;i<8;i++)
        #pragma unroll
        for (int j=0;j<8;j++) acc[i][j]=0.f;
    const int ar = tid>>2, ac = (tid&3)<<2;
    const int numT = (K+TBK-1)/TBK;
    for (int kt=0; kt<numT; kt++){
        const int k0 = kt*TBK;
        #pragma unroll
        for (int hh=0; hh<2; hh++){
            int row = rowBase + ar + hh*64, kg = k0 + ac;
            float4 av = make_float4(0,0,0,0);
            if (row < M){
                const float* ap = A + (size_t)row*K + kg;
                if (kg+3 < K) av = *(const float4*)ap;
                else { if(kg<K)av.x=ap[0]; if(kg+1<K)av.y=ap[1]; if(kg+2<K)av.z=ap[2]; }
            }
            As[(ac+0)*SP+ar+hh*64]=av.x; As[(ac+1)*SP+ar+hh*64]=av.y;
            As[(ac+2)*SP+ar+hh*64]=av.z; As[(ac+3)*SP+ar+hh*64]=av.w;
        }
        #pragma unroll
        for (int hh=0; hh<2; hh++){
            int kr = (tid>>5) + hh*8, c4 = (tid&31)<<2, kg = k0+kr;
            float4 bv = make_float4(0,0,0,0);
            if (kg < K) bv = *(const float4*)(Bm + (size_t)kg*N + colBase + c4);
            *(float4*)&Bs[kr*SP + c4] = bv;
        }
        __syncthreads();
        #pragma unroll
        for (int kk=0; kk<TBK; kk++){
            float4 a0 = *(const float4*)&As[kk*SP + ty*8];
            float4 a1 = *(const float4*)&As[kk*SP + ty*8 + 4];
            float4 b0 = *(const float4*)&Bs[kk*SP + tx*8];
            float4 b1 = *(const float4*)&Bs[kk*SP + tx*8 + 4];
            float av[8]={a0.x,a0.y,a0.z,a0.w,a1.x,a1.y,a1.z,a1.w};
            float bv[8]={b0.x,b0.y,b0.z,b0.w,b1.x,b1.y,b1.z,b1.w};
            #pragma unroll
            for (int i=0;i<8;i++)
                #pragma unroll
                for (int j=0;j<8;j++) acc[i][j] = fmaf(av[i], bv[j], acc[i][j]);
        }
        __syncthreads();
    }
    #pragma unroll
    for (int i=0;i<8;i++){
        int row = rowBase + ty*8 + i;
        if (row >= M) continue;
        float* cp = C + (size_t)row*N + colBase + tx*8;
        #pragma unroll
        for (int jj=0; jj<2; jj++)
            *(float4*)(cp+jj*4) = make_float4(acc[i][jj*4],acc[i][jj*4+1],acc[i][jj*4+2],acc[i][jj*4+3]);
    }
}

// ---- fused attention: softmax_d(q), softmax_L(kk), ctx=kk^T v, att0=q ctx (HMMA fp16)
#define AP 136
#define SM_ATTN ((3*48*AP + 128*AP)*2)
__global__ __launch_bounds__(256) void k_attn()
{
    extern __shared__ __half sma[];
    __half* s_q = sma;
    __half* s_k = sma + 48*AP;
    __half* s_v = sma + 2*48*AP;
    __half* s_c = sma + 3*48*AP;
    const int bn = blockIdx.x, tid = threadIdx.x;
    const int warp = tid>>5, lane = tid&31;
    const __half* qg = (const __half*)g_q  + (size_t)bn*C_NL*C_ND;
    const __half* kg = (const __half*)g_kk + (size_t)bn*C_NL*C_ND;
    const __half* vg = (const __half*)g_v  + (size_t)bn*C_NL*C_ND;
    // load 3 x 48x128 fp16 tiles (16B chunks)
    for (int i = tid; i < 3*768; i += 256){
        int t = i/768, j = i%768, row = j>>4, c8 = j&15;
        __half* dst = (t==0? s_q : t==1? s_k : s_v) + row*AP + c8*8;
        const __half* src = (t==0? qg : t==1? kg : vg) + row*C_ND + c8*8;
        *(uint4*)dst = *(const uint4*)src;
    }
    __syncthreads();
    // softmax q over d (rows), *d^-0.5
    for (int r = 0; r < 6; r++){
        int row = warp*6 + r;
        float v4[4];
        __half* p = s_q + row*AP + lane*4;
        #pragma unroll
        for (int i=0;i<4;i++) v4[i] = __half2float(p[i]);
        float m = fmaxf(fmaxf(v4[0],v4[1]), fmaxf(v4[2],v4[3]));
        #pragma unroll
        for (int o=16;o;o>>=1) m = fmaxf(m, __shfl_xor_sync(~0u, m, o));
        float e[4], s = 0.f;
        #pragma unroll
        for (int i=0;i<4;i++){ e[i] = expf(v4[i]-m); s += e[i]; }
        #pragma unroll
        for (int o=16;o;o>>=1) s += __shfl_xor_sync(~0u, s, o);
        float sc = 0.08838834764831845f / s;
        *(__half2*)(p)   = __floats2half2_rn(e[0]*sc, e[1]*sc);
        *(__half2*)(p+2) = __floats2half2_rn(e[2]*sc, e[3]*sc);
    }
    // softmax kk over L (cols)
    if (tid < 128){
        int c = tid;
        float v[C_NL], m = -1e30f;
        #pragma unroll
        for (int l=0;l<C_NL;l++){ v[l] = __half2float(s_k[l*AP + c]); m = fmaxf(m, v[l]); }
        float s = 0.f;
        #pragma unroll
        for (int l=0;l<C_NL;l++){ v[l] = expf(v[l]-m); s += v[l]; }
        float inv = 1.f/s;
        #pragma unroll
        for (int l=0;l<C_NL;l++) s_k[l*AP + c] = __float2half(v[l]*inv);
    }
    __syncthreads();
    // ctx = kk^T (128x48) @ v (48x128): warps 4m x 2n, warp tile 32x64, K=48
    {
        const int wm = warp&3, wn = warp>>2;
        float acc[2][8][4];
        #pragma unroll
        for (int i=0;i<2;i++)
            #pragma unroll
            for (int j=0;j<8;j++)
                #pragma unroll
                for (int q=0;q<4;q++) acc[i][j][q]=0.f;
        #pragma unroll
        for (int ks=0; ks<3; ks++){
            const int kc = ks*16;
            uint32_t a[2][4], bfr[8][2];
            #pragma unroll
            for (int mt=0; mt<2; mt++){
                int m0 = wm*32 + mt*16;
                int row = kc + (lane>>4)*8 + (lane&7);
                int col = m0 + ((lane>>3)&1)*8;
                LDSM4T(a[mt][0],a[mt][1],a[mt][2],a[mt][3], smem_u32(s_k + row*AP + col));
            }
            #pragma unroll
            for (int p=0; p<4; p++){
                int n0 = wn*64 + p*16;
                int row = kc + ((lane>>3)&1)*8 + (lane&7);
                int col = n0 + (lane>>4)*8;
                uint32_t r0,r1,r2,r3;
                LDSM4T(r0,r1,r2,r3, smem_u32(s_v + row*AP + col));
                bfr[p*2][0]=r0; bfr[p*2][1]=r1; bfr[p*2+1][0]=r2; bfr[p*2+1][1]=r3;
            }
            #pragma unroll
            for (int mt=0; mt<2; mt++)
                #pragma unroll
                for (int nt=0; nt<8; nt++)
                    MMA_F16(acc[mt][nt], a[mt], bfr[nt]);
        }
        const int g = lane>>2, tg = lane&3;
        #pragma unroll
        for (int mt=0; mt<2; mt++){
            int r0 = wm*32 + mt*16 + g;
            #pragma unroll
            for (int nt=0; nt<8; nt++){
                int c0 = wn*64 + nt*8 + tg*2;
                *(__half2*)(s_c + r0*AP + c0)     = __floats2half2_rn(acc[mt][nt][0], acc[mt][nt][1]);
                *(__half2*)(s_c + (r0+8)*AP + c0) = __floats2half2_rn(acc[mt][nt][2], acc[mt][nt][3]);
            }
        }
    }
    __syncthreads();
    // att0 = q (48x128) @ ctx (128x128): warps 3m x 2n (6 active), warp tile 16x64, K=128
    if (warp < 6){
        const int wm = warp>>1, wn = warp&1;
        const int m0 = wm*16;
        float acc[8][4];
        #pragma unroll
        for (int j=0;j<8;j++)
            #pragma unroll
            for (int q=0;q<4;q++) acc[j][q]=0.f;
        #pragma unroll
        for (int ks=0; ks<8; ks++){
            const int kc = ks*16;
            uint32_t a[4], bfr[8][2];
            {
                int row = m0 + (lane&7) + ((lane>>3)&1)*8;
                int col = kc + (lane>>4)*8;
                LDSM4(a[0],a[1],a[2],a[3], smem_u32(s_q + row*AP + col));
            }
            #pragma unroll
            for (int p=0; p<4; p++){
                int n0 = wn*64 + p*16;
                int row = kc + ((lane>>3)&1)*8 + (lane&7);
                int col = n0 + (lane>>4)*8;
                uint32_t r0,r1,r2,r3;
                LDSM4T(r0,r1,r2,r3, smem_u32(s_c + row*AP + col));
                bfr[p*2][0]=r0; bfr[p*2][1]=r1; bfr[p*2+1][0]=r2; bfr[p*2+1][1]=r3;
            }
            #pragma unroll
            for (int nt=0; nt<8; nt++)
                MMA_F16(acc[nt], a, bfr[nt]);
        }
        const int g = lane>>2, tg = lane&3;
        __half* ob = (__half*)g_ap + (size_t)bn*C_NL*C_ND;
        #pragma unroll
        for (int nt=0; nt<8; nt++){
            int c0 = wn*64 + nt*8 + tg*2;
            *(__half2*)(ob + (m0+g)*C_ND + c0)   = __floats2half2_rn(acc[nt][0], acc[nt][1]);
            *(__half2*)(ob + (m0+g+8)*C_ND + c0) = __floats2half2_rn(acc[nt][2], acc[nt][3]);
        }
    }
}

// ---------------- adj -> fp16 (scaled 1024) ----------------
__global__ __launch_bounds__(256) void k_split_adj_h(const float* __restrict__ adj)
{
    size_t idx = (size_t)blockIdx.x*256 + threadIdx.x;
    if (idx >= (size_t)MPAD*KPAD) return;
    int m = (int)(idx / KPAD), k = (int)(idx % KPAD);
    float v = (m < C_NN && k < C_NN) ? adj[(size_t)m*C_NN + k] * 1024.f : 0.f;
    ((__half*)g_a2)[idx] = __float2half(v);
}

// -------- build nf^T fp16 --------------------
__global__ __launch_bounds__(256) void k_bt_h(__nv_bfloat16* __restrict__ B2)
{
    __shared__ float sm[32][33];
    int n0 = blockIdx.x*32, d0 = blockIdx.y*32, bl = blockIdx.z;
    int b = bl / C_NL, l = bl % C_NL;
    int tx = threadIdx.x & 31, ty = threadIdx.x >> 5;
    #pragma unroll
    for (int s=0;s<4;s++){
        int n = n0 + ty + s*8;
        float v = 0.f;
        if (n < C_NN) v = g_enc[((size_t)(b*C_NN + n)*C_NL + l)*C_ND + d0 + tx];
        sm[ty+s*8][tx] = v;
    }
    __syncthreads();
    #pragma unroll
    for (int s=0;s<4;s++){
        int dl = ty + s*8;
        ((__half*)B2)[(size_t)(bl*C_ND + d0 + dl)*KPAD + n0 + tx] = __float2half(sm[tx][dl]);
    }
}

// ---------------- pack fp32 -> [Ah|Al|Ah] bf16 ----------------
__global__ __launch_bounds__(256) void k_packA(const float* __restrict__ A,
    __nv_bfloat16* __restrict__ Ap, int M, int K, int Mpad)
{
    size_t idx = (size_t)blockIdx.x*256 + threadIdx.x;
    if (idx >= (size_t)Mpad*K) return;
    int row = (int)(idx / K), k = (int)(idx % K);
    float v = (row < M) ? A[(size_t)row*K + k] : 0.f;
    __nv_bfloat16 h, lo; split_bf16(v, h, lo);
    __nv_bfloat16* p = Ap + (size_t)row*3*K + k;
    p[0] = h; p[K] = lo; p[2*K] = h;
}

// ---------------- pack weights [N][K] -> [Bh|Bh|Bl] ----------------
__global__ __launch_bounds__(256) void k_packB(const float* __restrict__ B,
    __nv_bfloat16* __restrict__ Bp, int N, int K)
{
    int idx = blockIdx.x*256 + threadIdx.x;
    if (idx >= N*K) return;
    int n = idx / K, k = idx % K;
    float v = B[(size_t)n*K + k];
    __nv_bfloat16 h, lo; split_bf16(v, h, lo);
    __nv_bfloat16* p = Bp + (size_t)n*3*K + k;
    p[0] = h; p[K] = h; p[2*K] = lo;
}

// --------- pack transposed weights [K][N] -> [Bh|Bh|Bl] ---------------------
__global__ __launch_bounds__(256) void k_packBt(const float* __restrict__ W,
    __nv_bfloat16* __restrict__ Bp, int N, int K)
{
    int idx = blockIdx.x*256 + threadIdx.x;
    if (idx >= N*K) return;
    int n = idx / K, k = idx % K;
    float v = W[(size_t)k*N + n];
    __nv_bfloat16 h, lo; split_bf16(v, h, lo);
    __nv_bfloat16* p = Bp + (size_t)n*3*K + k;
    p[0] = h; p[K] = h; p[2*K] = lo;
}

// ---------------- weight -> plain fp16 ----------------
__global__ __launch_bounds__(256) void k_packW_h(const float* __restrict__ W,
    __half* __restrict__ out, int nElem)
{
    int idx = blockIdx.x*256 + threadIdx.x;
    if (idx < nElem) out[idx] = __float2half(W[idx]);
}

// ---------------- generic HMMA GEMM: C[M][N] (+)= A @ B^T -------------------
// HALF: 0=bf16, 1=fp16.
// EPI: 0 store f32 | 2 +=x+bias | 3 +=x | 5 store x*oscale | 6 store fp16 | 7 gelu+bias->packed bf16
template<int EPI, int HALF>
__global__ __launch_bounds__(256) void hgemm(
    const __nv_bfloat16* __restrict__ A, const __nv_bfloat16* __restrict__ Bm,
    float* __restrict__ C, __nv_bfloat16* __restrict__ Cp,
    const float* __restrict__ bias,
    int Mreal, int N, int K, float oscale)
{
    __shared__ __nv_bfloat16 As[2][128*40];
    __shared__ __nv_bfloat16 Bs[2][128*40];
    const int tid = threadIdx.x;
    const int mBase = blockIdx.x*128, cBase = blockIdx.y*128;
    const __nv_bfloat16* pA = A + (size_t)mBase*K;
    const __nv_bfloat16* pB = Bm + (size_t)cBase*K;
    const int warp = tid>>5, lane = tid&31;
    const int wm = warp&3, wn = warp>>2;
    float acc[2][8][4];
    #pragma unroll
    for (int i=0;i<2;i++)
        #pragma unroll
        for (int j=0;j<8;j++)
            #pragma unroll
            for (int q=0;q<4;q++) acc[i][j][q] = 0.f;

    #define PREFETCH(ck, buf) do { \
        int _k0 = (ck)*32; \
        _Pragma("unroll") \
        for (int _t=0; _t<4; _t++){ \
            int _j = _t*256 + tid; \
            int _jj = _j & 511; \
            int _r = _jj>>2, _seg = _jj&3; \
            const __nv_bfloat16* _src = ((_j < 512) ? pA : pB) + (size_t)_r*K + _k0 + _seg*8; \
            uint32_t _dst = smem_u32(((_j < 512) ? &As[buf][0] : &Bs[buf][0]) + _r*40 + _seg*8); \
            CP_ASYNC16(_dst, _src); \
        } \
        CP_COMMIT(); \
    } while(0)

    const int nck = K >> 5;
    PREFETCH(0, 0);
    for (int ck = 0; ck < nck; ck++){
        if (ck + 1 < nck){ PREFETCH(ck+1, (ck+1)&1); CP_WAIT(1); }
        else             { CP_WAIT(0); }
        __syncthreads();
        const __nv_bfloat16* as = &As[ck&1][0];
        const __nv_bfloat16* bs = &Bs[ck&1][0];
        #pragma unroll
        for (int ks=0; ks<2; ks++){
            const int kc = ks*16;
            uint32_t a[2][4], bfr[8][2];
            #pragma unroll
            for (int mt=0; mt<2; mt++){
                int row = wm*32 + mt*16 + (lane&7) + ((lane>>3)&1)*8;
                int col = kc + (lane>>4)*8;
                LDSM4(a[mt][0], a[mt][1], a[mt][2], a[mt][3], smem_u32(as + row*40 + col));
            }
            #pragma unroll
            for (int p=0; p<4; p++){
                int row = wn*64 + p*16 + (lane>>4)*8 + (lane&7);
                int col = kc + ((lane>>3)&1)*8;
                uint32_t r0,r1,r2,r3;
                LDSM4(r0,r1,r2,r3, smem_u32(bs + row*40 + col));
                bfr[p*2][0]=r0; bfr[p*2][1]=r1; bfr[p*2+1][0]=r2; bfr[p*2+1][1]=r3;
            }
            #pragma unroll
            for (int mt=0; mt<2; mt++)
                #pragma unroll
                for (int nt=0; nt<8; nt++){
                    if (HALF) { MMA_F16(acc[mt][nt], a[mt], bfr[nt]); }
                    else      { MMA_BF16(acc[mt][nt], a[mt], bfr[nt]); }
                }
        }
        __syncthreads();
    }
    #undef PREFETCH

    const int g = lane>>2, tg = lane&3;
    #pragma unroll
    for (int mt=0; mt<2; mt++){
        int rbase = mBase + wm*32 + mt*16 + g;
        #pragma unroll
        for (int half=0; half<2; half++){
            int r = rbase + half*8;
            if (r >= Mreal) continue;
            #pragma unroll
            for (int nt=0; nt<8; nt++){
                int c0 = cBase + wn*64 + nt*8 + tg*2;
                float v0 = acc[mt][nt][half*2], v1 = acc[mt][nt][half*2+1];
                if (EPI == 6){
                    __half* pp = (__half*)Cp + (size_t)r*N + c0;
                    *(__half2*)pp = __floats2half2_rn(v0, v1);
                } else if (EPI == 7){
                    float g0 = geluf(v0 + bias[c0]), g1 = geluf(v1 + bias[c0+1]);
                    __nv_bfloat16 h0,l0,h1,l1;
                    split_bf16(g0,h0,l0); split_bf16(g1,h1,l1);
                    __nv_bfloat16* pp = Cp + (size_t)r*3*N + c0;
                    *(__nv_bfloat162*)(pp)       = __nv_bfloat162{h0,h1};
                    *(__nv_bfloat162*)(pp + N)   = __nv_bfloat162{l0,l1};
                    *(__nv_bfloat162*)(pp + 2*N) = __nv_bfloat162{h0,h1};
                } else {
                    float* cp = &C[(size_t)r*N + c0];
                    if (EPI == 0){
                        *(float2*)cp = make_float2(v0, v1);
                    } else if (EPI == 5){
                        *(float2*)cp = make_float2(v0*oscale, v1*oscale);
                    } else if (EPI == 2){
                        float2 c = *(float2*)cp;
                        *(float2*)cp = make_float2(c.x + v0 + bias[c0], c.y + v1 + bias[c0+1]);
                    } else {
                        float2 c = *(float2*)cp;
                        *(float2*)cp = make_float2(c.x + v0, c.y + v1);
                    }
                }
            }
        }
    }
}

// ---------------- grouped per-node GEMM (agg=g_ff, res=g_q) ----------------
#define SM_GRP ((128*132 + 96*128)*4)
__global__ __launch_bounds__(256) void k_group()
{
    extern __shared__ float sm[];
    float* s_w = sm;
    float* s_a = sm + 128*132;
    const int n = blockIdx.x, tid = threadIdx.x;
    const float* wb = g_pw + (size_t)n*C_ND*C_ND;
    const float* ab = g_ff + (size_t)n*C_BL*C_ND;
    for (int i = tid; i < (C_ND*C_ND)/4; i += 256){
        int e = i<<2, r = e>>7, c = e&127;
        *(float4*)&s_w[r*132+c] = *(const float4*)(wb+e);
    }
    for (int i = tid; i < (C_BL*C_ND)/4; i += 256)
        ((float4*)s_a)[i] = ((const float4*)ab)[i];
    __syncthreads();
    const int ty = tid>>4, tx = tid&15;
    float acc[6][8];
    #pragma unroll
    for (int i=0;i<6;i++)
        #pragma unroll
        for (int j=0;j<8;j++) acc[i][j]=0.f;
    #pragma unroll 4
    for (int k=0;k<C_ND;k++){
        float4 b0 = *(const float4*)&s_w[k*132 + tx*8];
        float4 b1 = *(const float4*)&s_w[k*132 + tx*8+4];
        float bv[8]={b0.x,b0.y,b0.z,b0.w,b1.x,b1.y,b1.z,b1.w};
        #pragma unroll
        for (int i=0;i<6;i++){
            float a = s_a[(ty*6+i)*C_ND + k];
            #pragma unroll
            for (int j=0;j<8;j++) acc[i][j] = fmaf(a, bv[j], acc[i][j]);
        }
    }
    float* ob = g_q + (size_t)n*C_BL*C_ND;
    #pragma unroll
    for (int i=0;i<6;i++){
        #pragma unroll
        for (int jj=0;jj<2;jj++){
            float4 vv = make_float4(acc[i][jj*4],acc[i][jj*4+1],acc[i][jj*4+2],acc[i][jj*4+3]);
            *(float4*)(ob + (ty*6+i)*C_ND + tx*8 + jj*4) = vv;
        }
    }
}

// ---------------- GroupNorm stats ----------------
__global__ __launch_bounds__(256) void k_gnred()
{
    int bl = blockIdx.x>>2, g = blockIdx.x&3;
    int base = bl*C_ND + g*32;
    float s = 0.f, ss = 0.f;
    for (int i = threadIdx.x; i < C_NN*32; i += 256){
        int n = i>>5, o = i&31;
        float v = g_q[(size_t)n*C_BL*C_ND + base + o];
        s += v; ss += v*v;
    }
    __shared__ float r1[256], r2[256];
    r1[threadIdx.x]=s; r2[threadIdx.x]=ss; __syncthreads();
    for (int st=128; st>0; st>>=1){
        if (threadIdx.x < st){ r1[threadIdx.x]+=r1[threadIdx.x+st]; r2[threadIdx.x]+=r2[threadIdx.x+st]; }
        __syncthreads();
    }
    if (threadIdx.x == 0){
        float mean = r1[0]/(C_NN*32.0f);
        float var = r2[0]/(C_NN*32.0f) - mean*mean;
        g_gmu[blockIdx.x] = mean;
        g_grs[blockIdx.x] = rsqrtf(var + 1e-5f);
    }
}

// ---------------- final fused ----------------
__global__ __launch_bounds__(128) void k_final(
    const float* __restrict__ gn_g, const float* __restrict__ gn_b,
    const float* __restrict__ p2_w, const float* __restrict__ p2_b,
    const float* __restrict__ p1_w, const float* __restrict__ p1_b,
    float* __restrict__ out)
{
    int bn = blockIdx.x, b = bn / C_NN, n = bn % C_NN;
    int lane = threadIdx.x & 31, warp = threadIdx.x >> 5;
    __shared__ float s_s[C_NL];
    int d0 = lane*4, g = d0 >> 5;
    float4 gg = *(const float4*)(gn_g + d0);
    float4 gb = *(const float4*)(gn_b + d0);
    float4 pw = *(const float4*)(p2_w + d0);
    float p2b = p2_b[0];
    for (int l = warp; l < C_NL; l += 4){
        int bl = b*C_NL + l;
        float mu = g_gmu[bl*4 + g], rs = g_grs[bl*4 + g];
        float4 x = *(const float4*)(g_q + (size_t)n*C_BL*C_ND + bl*C_ND + d0);
        float dot = ((x.x-mu)*rs*gg.x+gb.x)*pw.x + ((x.y-mu)*rs*gg.y+gb.y)*pw.y
                  + ((x.z-mu)*rs*gg.z+gb.z)*pw.z + ((x.w-mu)*rs*gg.w+gb.w)*pw.w;
        #pragma unroll
        for (int o=16;o;o>>=1) dot += __shfl_xor_sync(~0u, dot, o);
        if (lane == 0){
            float sv = dot + p2b;
            s_s[l] = sv / (1.f + expf(-sv));
        }
    }
    __syncthreads();
    if (threadIdx.x < C_NLOUT){
        float acc = p1_b[threadIdx.x];
        #pragma unroll
        for (int l=0;l<C_NL;l++) acc = fmaf(p1_w[threadIdx.x*C_NL + l], s_s[l], acc);
        out[(size_t)b*C_NLOUT*C_NN + threadIdx.x*C_NN + n] = acc + g_mean[bn];
    }
}

// ---------------- driver ----------------
extern "C" void kernel_launch(void* const* d_in, const int* in_sizes, int n_in,
                              void* d_out, int out_size)
{
    const float* x_enc = (const float*)d_in[0];
    const float* adj   = (const float*)d_in[1];
    const float* pe_raw= (const float*)d_in[2];
    const float* conv_w= (const float*)d_in[3];
    const float* pos_w = (const float*)d_in[4];
    const float* pos_b = (const float*)d_in[5];
    const float* wq    = (const float*)d_in[6];
    const float* wk    = (const float*)d_in[7];
    const float* wv    = (const float*)d_in[8];
    const float* wo    = (const float*)d_in[9];
    const float* ln1_g = (const float*)d_in[10];
    const float* ln1_b = (const float*)d_in[11];
    const float* ff_w1 = (const float*)d_in[12];
    const float* ff_b1 = (const float*)d_in[13];
    const float* ff_w2 = (const float*)d_in[14];
    const float* ff_b2 = (const float*)d_in[15];
    const float* ln2_g = (const float*)d_in[16];
    const float* ln2_b = (const float*)d_in[17];
    const float* wpool = (const float*)d_in[18];
    const float* gn_g  = (const float*)d_in[19];
    const float* gn_b  = (const float*)d_in[20];
    const float* p2_w  = (const float*)d_in[21];
    const float* p2_b  = (const float*)d_in[22];
    const float* p1_w  = (const float*)d_in[23];
    const float* p1_b  = (const float*)d_in[24];
    float* out = (float*)d_out;

    cudaFuncSetAttribute(k_attn,  cudaFuncAttributeMaxDynamicSharedMemorySize, SM_ATTN);
    cudaFuncSetAttribute(k_group, cudaFuncAttributeMaxDynamicSharedMemorySize, SM_GRP);

    float *penc, *pq, *pkk, *pv, *pff, *ppe, *ppe2, *ppw;
    __nv_bfloat16 *pa2, *pb2, *pap, *pbp;
    cudaGetSymbolAddress((void**)&penc,  g_enc);
    cudaGetSymbolAddress((void**)&pq,    g_q);
    cudaGetSymbolAddress((void**)&pkk,   g_kk);
    cudaGetSymbolAddress((void**)&pv,    g_v);
    cudaGetSymbolAddress((void**)&pff,   g_ff);
    cudaGetSymbolAddress((void**)&ppe,   g_pe);
    cudaGetSymbolAddress((void**)&ppe2,  g_pe2);
    cudaGetSymbolAddress((void**)&ppw,   g_pw);
    cudaGetSymbolAddress((void**)&pa2,   g_a2);
    cudaGetSymbolAddress((void**)&pb2,   g_b2);
    cudaGetSymbolAddress((void**)&pap,   g_ap);
    cudaGetSymbolAddress((void**)&pbp,   g_bp);

    float* pagg = pff;               // spatial agg aliases g_ff
    __half* pap16 = (__half*)pap;
    __half* pbp16 = (__half*)pbp;

    k_embed<<<C_BN, 128>>>(x_enc, conv_w);
    k_pe<<<(C_NN*C_ND + 255)/256, 256>>>(pe_raw, pos_w, pos_b);
    k_split_adj_h<<<(int)(((size_t)MPAD*KPAD + 255)/256), 256>>>(adj);

    // LN1 -> fp16; q/k/v projections (fp16, K=128) -> fp16 outputs
    k_ln_h<<<C_ROWS/8, 256>>>(penc, ln1_g, ln1_b, pap16);
    dim3 gP(C_ROWS/128, 1);
    k_packW_h<<<(128*128+255)/256, 256>>>(wq, pbp16, 128*128);
    hgemm<6,1><<<gP, 256>>>(pap, pbp, nullptr, (__nv_bfloat16*)pq, nullptr, C_ROWS, 128, 128, 1.f);
    k_packW_h<<<(128*128+255)/256, 256>>>(wk, pbp16, 128*128);
    hgemm<6,1><<<gP, 256>>>(pap, pbp, nullptr, (__nv_bfloat16*)pkk, nullptr, C_ROWS, 128, 128, 1.f);
    k_packW_h<<<(128*128+255)/256, 256>>>(wv, pbp16, 128*128);
    hgemm<6,1><<<gP, 256>>>(pap, pbp, nullptr, (__nv_bfloat16*)pv, nullptr, C_ROWS, 128, 128, 1.f);

    // fused softmaxes + HMMA attention core -> fp16 att0 in g_ap
    k_attn<<<C_BN, 256, SM_ATTN>>>();

    // enc += att0 @ wo^T (fp16, K=128)
    k_packW_h<<<(128*128+255)/256, 256>>>(wo, pbp16, 128*128);
    hgemm<3,1><<<gP, 256>>>(pap, pbp, penc, nullptr, nullptr, C_ROWS, 128, 128, 1.f);

    // FF block (protected): LN2 -> packed bf16; FF1 split-K3 gelu -> packed; FF2 split-K3
    k_ln_pack<<<C_ROWS/8, 256>>>(penc, ln2_g, ln2_b, pap);
    k_packB<<<(512*128+255)/256, 256>>>(ff_w1, pbp, 512, 128);
    hgemm<7,0><<<dim3(C_ROWS/128, 4), 256>>>(pap, pbp, nullptr, pb2, ff_b1, C_ROWS, 512, 384, 1.f);
    k_packB<<<(128*512+255)/256, 256>>>(ff_w2, pbp, 128, 512);
    hgemm<2,0><<<gP, 256>>>(pb2, pbp, penc, nullptr, ff_b2, C_ROWS, 128, 1536, 1.f);

    // spatial: agg = adj @ nf  (plain fp16, scaled)
    k_bt_h<<<dim3(KPAD/32, C_ND/32, C_BL), 256>>>(pb2);
    hgemm<5,1><<<dim3(MPAD/128, NCOL/128), 256>>>(pa2, pb2, pagg, nullptr, nullptr,
                                                  C_NN, NCOL, KPAD, 1.f/1024.f);

    // pe2 = adj @ pe (fp32); pw = pe2 @ wpool (bf16 split-K3, protected)
    sgemm_nn<<<dim3(24, 1), 256>>>(adj, ppe, ppe2, C_NN, 128, C_NN);
    k_packA<<<(int)(((size_t)MPAD*128 + 255)/256), 256>>>(ppe2, pap, C_NN, 128, MPAD);
    k_packBt<<<(16384*128+255)/256, 256>>>(wpool, pbp, 16384, 128);
    hgemm<0,0><<<dim3(MPAD/128, 128), 256>>>(pap, pbp, ppw, nullptr, nullptr, C_NN, 16384, 384, 1.f);

    k_group<<<C_NN, 256, SM_GRP>>>();
    k_gnred<<<C_BL*4, 256>>>();
    k_final<<<C_BN, 128>>>(gn_g, gn_b, p2_w, p2_b, p1_w, p1_b, out);
}

// round 14
// speedup vs baseline: 1.4513x; 1.4513x over previous
#include <cuda_runtime.h>
#include <cuda_bf16.h>
#include <cuda_fp16.h>
#include <math.h>
#include <stdint.h>

#define C_NB 2
#define C_NL 48
#define C_NN 3000
#define C_ND 128
#define C_NLOUT 24
#define C_BN (C_NB*C_NN)
#define C_ROWS (C_BN*C_NL)
#define C_BL (C_NB*C_NL)
#define KPAD 3008
#define MPAD 3072
#define NCOL (C_BL*C_ND)   // 12288

// ---------------- device-global scratch (aliased) ----------------
__device__ float g_mean[C_BN];
__device__ float g_enc [C_ROWS*C_ND];
__device__ float g_q   [C_ROWS*C_ND];          // fp32 res (spatial output)
__device__ float g_ff  [C_ROWS*512];           // also: g_agg
__device__ float g_pe  [C_NN*C_ND];
__device__ float g_pe2 [C_NN*C_ND];
__device__ float g_pw  [(size_t)C_NN*C_ND*C_ND];
__device__ float g_gmu [C_BL*4];
__device__ float g_grs [C_BL*4];
__device__ __nv_bfloat16 g_a2 [(size_t)MPAD*KPAD];     // fp16 bits (adj*1024)
__device__ __nv_bfloat16 g_b2 [(size_t)C_ROWS*1536];   // qkv fp16 / FF1 packed / nf^T fp16
__device__ __nv_bfloat16 g_ap [(size_t)C_ROWS*384];    // LN outs / att0 / packed pe2
__device__ __nv_bfloat16 g_bp [(size_t)16384*384];     // packed weights

__device__ __forceinline__ float geluf(float x){
    return 0.5f*x*(1.0f+erff(x*0.70710678118654752f));
}
__device__ __forceinline__ uint32_t smem_u32(const void* p){
    uint32_t a;
    asm("{ .reg .u64 t; cvta.to.shared.u64 t, %1; cvt.u32.u64 %0, t; }" : "=r"(a) : "l"(p));
    return a;
}
__device__ __forceinline__ void split_bf16(float v, __nv_bfloat16& h, __nv_bfloat16& lo){
    h = __float2bfloat16(v);
    lo = __float2bfloat16(v - __bfloat162float(h));
}
#define CP_ASYNC16(dst, src) asm volatile("cp.async.cg.shared.global [%0], [%1], 16;" :: "r"(dst), "l"(src))
#define CP_COMMIT() asm volatile("cp.async.commit_group;" ::: "memory")
#define CP_WAIT(n)  asm volatile("cp.async.wait_group %0;" :: "n"(n) : "memory")
#define LDSM4(r0,r1,r2,r3,addr) \
    asm volatile("ldmatrix.sync.aligned.m8n8.x4.shared.b16 {%0,%1,%2,%3}, [%4];" \
        : "=r"(r0),"=r"(r1),"=r"(r2),"=r"(r3) : "r"(addr))
#define LDSM4T(r0,r1,r2,r3,addr) \
    asm volatile("ldmatrix.sync.aligned.m8n8.x4.trans.shared.b16 {%0,%1,%2,%3}, [%4];" \
        : "=r"(r0),"=r"(r1),"=r"(r2),"=r"(r3) : "r"(addr))
#define MMA_BF16(d, a, b) asm volatile( \
    "mma.sync.aligned.m16n8k16.row.col.f32.bf16.bf16.f32 " \
    "{%0,%1,%2,%3}, {%4,%5,%6,%7}, {%8,%9}, {%0,%1,%2,%3};" \
    : "+f"((d)[0]),"+f"((d)[1]),"+f"((d)[2]),"+f"((d)[3]) \
    : "r"((a)[0]),"r"((a)[1]),"r"((a)[2]),"r"((a)[3]), "r"((b)[0]),"r"((b)[1]))
#define MMA_F16(d, a, b) asm volatile( \
    "mma.sync.aligned.m16n8k16.row.col.f32.f16.f16.f32 " \
    "{%0,%1,%2,%3}, {%4,%5,%6,%7}, {%8,%9}, {%0,%1,%2,%3};" \
    : "+f"((d)[0]),"+f"((d)[1]),"+f"((d)[2]),"+f"((d)[3]) \
    : "r"((a)[0]),"r"((a)[1]),"r"((a)[2]),"r"((a)[3]), "r"((b)[0]),"r"((b)[1]))

// ---------------- K1: mean + circular conv1d embedding ----------------
__global__ __launch_bounds__(128) void k_embed(const float* __restrict__ x_enc,
                                               const float* __restrict__ conv_w)
{
    int bn = blockIdx.x, b = bn / C_NN, n = bn % C_NN, t = threadIdx.x;
    __shared__ float red[128];
    __shared__ float xs[C_NL+2];
    float v = 0.f;
    if (t < C_NL) v = x_enc[(size_t)(b*C_NL + t)*C_NN + n];
    red[t] = v; __syncthreads();
    #pragma unroll
    for (int s = 64; s > 0; s >>= 1) { if (t < s) red[t] += red[t+s]; __syncthreads(); }
    float mean = red[0] * (1.f/C_NL);
    if (t == 0) g_mean[bn] = mean;
    if (t < C_NL) xs[t+1] = v - mean;
    __syncthreads();
    if (t == 0) { xs[0] = xs[C_NL]; xs[C_NL+1] = xs[1]; }
    __syncthreads();
    float w0 = conv_w[t*3], w1 = conv_w[t*3+1], w2 = conv_w[t*3+2];
    float* out = g_enc + (size_t)bn*C_NL*C_ND;
    #pragma unroll 4
    for (int l = 0; l < C_NL; l++)
        out[l*C_ND + t] = w0*xs[l] + w1*xs[l+1] + w2*xs[l+2];
}

// ---------------- pe projection ----------------
__global__ __launch_bounds__(256) void k_pe(const float* __restrict__ pe_raw,
    const float* __restrict__ pos_w, const float* __restrict__ pos_b)
{
    int idx = blockIdx.x*256 + threadIdx.x;
    if (idx >= C_NN*C_ND) return;
    int n = idx >> 7, d = idx & 127;
    g_pe[idx] = pe_raw[n]*pos_w[d*3] + pe_raw[C_NN+n]*pos_w[d*3+1]
              + pe_raw[2*C_NN+n]*pos_w[d*3+2] + pos_b[d];
}

// ---------------- LayerNorm -> fp16 row ----------------
__global__ __launch_bounds__(256) void k_ln_h(const float* __restrict__ in,
    const float* __restrict__ ga, const float* __restrict__ be,
    __half* __restrict__ outp)
{
    int row = blockIdx.x*8 + (threadIdx.x>>5), lane = threadIdx.x & 31;
    float4 x = *(const float4*)(in + (size_t)row*C_ND + lane*4);
    float s = x.x+x.y+x.z+x.w;
    #pragma unroll
    for (int o=16;o;o>>=1) s += __shfl_xor_sync(~0u, s, o);
    float mean = s*(1.f/128.f);
    float dx=x.x-mean, dy=x.y-mean, dz=x.z-mean, dw=x.w-mean;
    float sq = dx*dx+dy*dy+dz*dz+dw*dw;
    #pragma unroll
    for (int o=16;o;o>>=1) sq += __shfl_xor_sync(~0u, sq, o);
    float rstd = rsqrtf(sq*(1.f/128.f) + 1e-5f);
    float4 g = *(const float4*)(ga + lane*4), bb = *(const float4*)(be + lane*4);
    __half* p = outp + (size_t)row*C_ND + lane*4;
    *(__half2*)(p)   = __floats2half2_rn(dx*rstd*g.x+bb.x, dy*rstd*g.y+bb.y);
    *(__half2*)(p+2) = __floats2half2_rn(dz*rstd*g.z+bb.z, dw*rstd*g.w+bb.w);
}

// ---------------- LayerNorm -> packed bf16 [h|lo|h] ----------------
__global__ __launch_bounds__(256) void k_ln_pack(const float* __restrict__ in,
    const float* __restrict__ ga, const float* __restrict__ be,
    __nv_bfloat16* __restrict__ outp)
{
    int row = blockIdx.x*8 + (threadIdx.x>>5), lane = threadIdx.x & 31;
    float4 x = *(const float4*)(in + (size_t)row*C_ND + lane*4);
    float s = x.x+x.y+x.z+x.w;
    #pragma unroll
    for (int o=16;o;o>>=1) s += __shfl_xor_sync(~0u, s, o);
    float mean = s*(1.f/128.f);
    float dx=x.x-mean, dy=x.y-mean, dz=x.z-mean, dw=x.w-mean;
    float sq = dx*dx+dy*dy+dz*dz+dw*dw;
    #pragma unroll
    for (int o=16;o;o>>=1) sq += __shfl_xor_sync(~0u, sq, o);
    float rstd = rsqrtf(sq*(1.f/128.f) + 1e-5f);
    float4 g = *(const float4*)(ga + lane*4), bb = *(const float4*)(be + lane*4);
    float vv[4] = { dx*rstd*g.x+bb.x, dy*rstd*g.y+bb.y, dz*rstd*g.z+bb.z, dw*rstd*g.w+bb.w };
    __nv_bfloat16 h[4], lo[4];
    #pragma unroll
    for (int i=0;i<4;i++) split_bf16(vv[i], h[i], lo[i]);
    __nv_bfloat16* p = outp + (size_t)row*384 + lane*4;
    *(__nv_bfloat162*)(p)     = __nv_bfloat162{h[0],h[1]};
    *(__nv_bfloat162*)(p+2)   = __nv_bfloat162{h[2],h[3]};
    *(__nv_bfloat162*)(p+128) = __nv_bfloat162{lo[0],lo[1]};
    *(__nv_bfloat162*)(p+130) = __nv_bfloat162{lo[2],lo[3]};
    *(__nv_bfloat162*)(p+256) = __nv_bfloat162{h[0],h[1]};
    *(__nv_bfloat162*)(p+258) = __nv_bfloat162{h[2],h[3]};
}

// ---------------- tiled fp32 SGEMM (pe2 only) ----------------
#define TBK 16
#define SP 132
__global__ __launch_bounds__(256) void sgemm_nn(
    const float* __restrict__ A, const float* __restrict__ Bm,
    float* __restrict__ C, int M, int N, int K)
{
    __shared__ float As[TBK*SP];
    __shared__ float Bs[TBK*SP];
    const int tid = threadIdx.x, ty = tid>>4, tx = tid&15;
    const int rowBase = blockIdx.x*128, colBase = blockIdx.y*128;
    float acc[8][8];
    #pragma unroll
    for (int i=0;i<8;i++)
        #pragma unroll
        for (int j=0;j<8;j++) acc[i][j]=0.f;
    const int ar = tid>>2, ac = (tid&3)<<2;
    const int numT = (K+TBK-1)/TBK;
    for (int kt=0; kt<numT; kt++){
        const int k0 = kt*TBK;
        #pragma unroll
        for (int hh=0; hh<2; hh++){
            int row = rowBase + ar + hh*64, kg = k0 + ac;
            float4 av = make_float4(0,0,0,0);
            if (row < M){
                const float* ap = A + (size_t)row*K + kg;
                if (kg+3 < K) av = *(const float4*)ap;
                else { if(kg<K)av.x=ap[0]; if(kg+1<K)av.y=ap[1]; if(kg+2<K)av.z=ap[2]; }
            }
            As[(ac+0)*SP+ar+hh*64]=av.x; As[(ac+1)*SP+ar+hh*64]=av.y;
            As[(ac+2)*SP+ar+hh*64]=av.z; As[(ac+3)*SP+ar+hh*64]=av.w;
        }
        #pragma unroll
        for (int hh=0; hh<2; hh++){
            int kr = (tid>>5) + hh*8, c4 = (tid&31)<<2, kg = k0+kr;
            float4 bv = make_float4(0,0,0,0);
            if (kg < K) bv = *(const float4*)(Bm + (size_t)kg*N + colBase + c4);
            *(float4*)&Bs[kr*SP + c4] = bv;
        }
        __syncthreads();
        #pragma unroll
        for (int kk=0; kk<TBK; kk++){
            float4 a0 = *(const float4*)&As[kk*SP + ty*8];
            float4 a1 = *(const float4*)&As[kk*SP + ty*8 + 4];
            float4 b0 = *(const float4*)&Bs[kk*SP + tx*8];
            float4 b1 = *(const float4*)&Bs[kk*SP + tx*8 + 4];
            float av[8]={a0.x,a0.y,a0.z,a0.w,a1.x,a1.y,a1.z,a1.w};
            float bv[8]={b0.x,b0.y,b0.z,b0.w,b1.x,b1.y,b1.z,b1.w};
            #pragma unroll
            for (int i=0;i<8;i++)
                #pragma unroll
                for (int j=0;j<8;j++) acc[i][j] = fmaf(av[i], bv[j], acc[i][j]);
        }
        __syncthreads();
    }
    #pragma unroll
    for (int i=0;i<8;i++){
        int row = rowBase + ty*8 + i;
        if (row >= M) continue;
        float* cp = C + (size_t)row*N + colBase + tx*8;
        #pragma unroll
        for (int jj=0; jj<2; jj++)
            *(float4*)(cp+jj*4) = make_float4(acc[i][jj*4],acc[i][jj*4+1],acc[i][jj*4+2],acc[i][jj*4+3]);
    }
}

// ---- fused attention over qkv[row][384]: softmaxes + ctx + att0 (HMMA fp16)
#define AP 136
#define SM_ATTN ((3*48*AP + 128*AP)*2)
__global__ __launch_bounds__(256) void k_attn(const __half* __restrict__ qkv)
{
    extern __shared__ __half sma[];
    __half* s_q = sma;
    __half* s_k = sma + 48*AP;
    __half* s_v = sma + 2*48*AP;
    __half* s_c = sma + 3*48*AP;
    const int bn = blockIdx.x, tid = threadIdx.x;
    const int warp = tid>>5, lane = tid&31;
    const __half* base = qkv + (size_t)bn*C_NL*384;
    // load q/k/v slices of 48x384 rows (16B chunks)
    for (int i = tid; i < 3*768; i += 256){
        int t = i/768, j = i%768, row = j>>4, c8 = j&15;
        __half* dst = (t==0? s_q : t==1? s_k : s_v) + row*AP + c8*8;
        const __half* src = base + row*384 + t*128 + c8*8;
        *(uint4*)dst = *(const uint4*)src;
    }
    __syncthreads();
    // softmax q over d, *d^-0.5
    for (int r = 0; r < 6; r++){
        int row = warp*6 + r;
        float v4[4];
        __half* p = s_q + row*AP + lane*4;
        #pragma unroll
        for (int i=0;i<4;i++) v4[i] = __half2float(p[i]);
        float m = fmaxf(fmaxf(v4[0],v4[1]), fmaxf(v4[2],v4[3]));
        #pragma unroll
        for (int o=16;o;o>>=1) m = fmaxf(m, __shfl_xor_sync(~0u, m, o));
        float e[4], s = 0.f;
        #pragma unroll
        for (int i=0;i<4;i++){ e[i] = expf(v4[i]-m); s += e[i]; }
        #pragma unroll
        for (int o=16;o;o>>=1) s += __shfl_xor_sync(~0u, s, o);
        float sc = 0.08838834764831845f / s;
        *(__half2*)(p)   = __floats2half2_rn(e[0]*sc, e[1]*sc);
        *(__half2*)(p+2) = __floats2half2_rn(e[2]*sc, e[3]*sc);
    }
    // softmax kk over L (cols)
    if (tid < 128){
        int c = tid;
        float v[C_NL], m = -1e30f;
        #pragma unroll
        for (int l=0;l<C_NL;l++){ v[l] = __half2float(s_k[l*AP + c]); m = fmaxf(m, v[l]); }
        float s = 0.f;
        #pragma unroll
        for (int l=0;l<C_NL;l++){ v[l] = expf(v[l]-m); s += v[l]; }
        float inv = 1.f/s;
        #pragma unroll
        for (int l=0;l<C_NL;l++) s_k[l*AP + c] = __float2half(v[l]*inv);
    }
    __syncthreads();
    // ctx = kk^T (128x48) @ v (48x128)
    {
        const int wm = warp&3, wn = warp>>2;
        float acc[2][8][4];
        #pragma unroll
        for (int i=0;i<2;i++)
            #pragma unroll
            for (int j=0;j<8;j++)
                #pragma unroll
                for (int q=0;q<4;q++) acc[i][j][q]=0.f;
        #pragma unroll
        for (int ks=0; ks<3; ks++){
            const int kc = ks*16;
            uint32_t a[2][4], bfr[8][2];
            #pragma unroll
            for (int mt=0; mt<2; mt++){
                int m0 = wm*32 + mt*16;
                int row = kc + (lane>>4)*8 + (lane&7);
                int col = m0 + ((lane>>3)&1)*8;
                LDSM4T(a[mt][0],a[mt][1],a[mt][2],a[mt][3], smem_u32(s_k + row*AP + col));
            }
            #pragma unroll
            for (int p=0; p<4; p++){
                int n0 = wn*64 + p*16;
                int row = kc + ((lane>>3)&1)*8 + (lane&7);
                int col = n0 + (lane>>4)*8;
                uint32_t r0,r1,r2,r3;
                LDSM4T(r0,r1,r2,r3, smem_u32(s_v + row*AP + col));
                bfr[p*2][0]=r0; bfr[p*2][1]=r1; bfr[p*2+1][0]=r2; bfr[p*2+1][1]=r3;
            }
            #pragma unroll
            for (int mt=0; mt<2; mt++)
                #pragma unroll
                for (int nt=0; nt<8; nt++)
                    MMA_F16(acc[mt][nt], a[mt], bfr[nt]);
        }
        const int g = lane>>2, tg = lane&3;
        #pragma unroll
        for (int mt=0; mt<2; mt++){
            int r0 = wm*32 + mt*16 + g;
            #pragma unroll
            for (int nt=0; nt<8; nt++){
                int c0 = wn*64 + nt*8 + tg*2;
                *(__half2*)(s_c + r0*AP + c0)     = __floats2half2_rn(acc[mt][nt][0], acc[mt][nt][1]);
                *(__half2*)(s_c + (r0+8)*AP + c0) = __floats2half2_rn(acc[mt][nt][2], acc[mt][nt][3]);
            }
        }
    }
    __syncthreads();
    // att0 = q (48x128) @ ctx (128x128)
    if (warp < 6){
        const int wm = warp>>1, wn = warp&1;
        const int m0 = wm*16;
        float acc[8][4];
        #pragma unroll
        for (int j=0;j<8;j++)
            #pragma unroll
            for (int q=0;q<4;q++) acc[j][q]=0.f;
        #pragma unroll
        for (int ks=0; ks<8; ks++){
            const int kc = ks*16;
            uint32_t a[4], bfr[8][2];
            {
                int row = m0 + (lane&7) + ((lane>>3)&1)*8;
                int col = kc + (lane>>4)*8;
                LDSM4(a[0],a[1],a[2],a[3], smem_u32(s_q + row*AP + col));
            }
            #pragma unroll
            for (int p=0; p<4; p++){
                int n0 = wn*64 + p*16;
                int row = kc + ((lane>>3)&1)*8 + (lane&7);
                int col = n0 + (lane>>4)*8;
                uint32_t r0,r1,r2,r3;
                LDSM4T(r0,r1,r2,r3, smem_u32(s_c + row*AP + col));
                bfr[p*2][0]=r0; bfr[p*2][1]=r1; bfr[p*2+1][0]=r2; bfr[p*2+1][1]=r3;
            }
            #pragma unroll
            for (int nt=0; nt<8; nt++)
                MMA_F16(acc[nt], a, bfr[nt]);
        }
        const int g = lane>>2, tg = lane&3;
        __half* ob = (__half*)g_ap + (size_t)bn*C_NL*C_ND;
        #pragma unroll
        for (int nt=0; nt<8; nt++){
            int c0 = wn*64 + nt*8 + tg*2;
            *(__half2*)(ob + (m0+g)*C_ND + c0)   = __floats2half2_rn(acc[nt][0], acc[nt][1]);
            *(__half2*)(ob + (m0+g+8)*C_ND + c0) = __floats2half2_rn(acc[nt][2], acc[nt][3]);
        }
    }
}

// ---------------- adj -> fp16 (scaled 1024) ----------------
__global__ __launch_bounds__(256) void k_split_adj_h(const float* __restrict__ adj)
{
    size_t idx = (size_t)blockIdx.x*256 + threadIdx.x;
    if (idx >= (size_t)MPAD*KPAD) return;
    int m = (int)(idx / KPAD), k = (int)(idx % KPAD);
    float v = (m < C_NN && k < C_NN) ? adj[(size_t)m*C_NN + k] * 1024.f : 0.f;
    ((__half*)g_a2)[idx] = __float2half(v);
}

// -------- build nf^T fp16 --------------------
__global__ __launch_bounds__(256) void k_bt_h(__nv_bfloat16* __restrict__ B2)
{
    __shared__ float sm[32][33];
    int n0 = blockIdx.x*32, d0 = blockIdx.y*32, bl = blockIdx.z;
    int b = bl / C_NL, l = bl % C_NL;
    int tx = threadIdx.x & 31, ty = threadIdx.x >> 5;
    #pragma unroll
    for (int s=0;s<4;s++){
        int n = n0 + ty + s*8;
        float v = 0.f;
        if (n < C_NN) v = g_enc[((size_t)(b*C_NN + n)*C_NL + l)*C_ND + d0 + tx];
        sm[ty+s*8][tx] = v;
    }
    __syncthreads();
    #pragma unroll
    for (int s=0;s<4;s++){
        int dl = ty + s*8;
        ((__half*)B2)[(size_t)(bl*C_ND + d0 + dl)*KPAD + n0 + tx] = __float2half(sm[tx][dl]);
    }
}

// ---------------- pack fp32 -> [Ah|Al|Ah] bf16 ----------------
__global__ __launch_bounds__(256) void k_packA(const float* __restrict__ A,
    __nv_bfloat16* __restrict__ Ap, int M, int K, int Mpad)
{
    size_t idx = (size_t)blockIdx.x*256 + threadIdx.x;
    if (idx >= (size_t)Mpad*K) return;
    int row = (int)(idx / K), k = (int)(idx % K);
    float v = (row < M) ? A[(size_t)row*K + k] : 0.f;
    __nv_bfloat16 h, lo; split_bf16(v, h, lo);
    __nv_bfloat16* p = Ap + (size_t)row*3*K + k;
    p[0] = h; p[K] = lo; p[2*K] = h;
}

// ---------------- pack weights [N][K] -> [Bh|Bh|Bl] ----------------
__global__ __launch_bounds__(256) void k_packB(const float* __restrict__ B,
    __nv_bfloat16* __restrict__ Bp, int N, int K)
{
    int idx = blockIdx.x*256 + threadIdx.x;
    if (idx >= N*K) return;
    int n = idx / K, k = idx % K;
    float v = B[(size_t)n*K + k];
    __nv_bfloat16 h, lo; split_bf16(v, h, lo);
    __nv_bfloat16* p = Bp + (size_t)n*3*K + k;
    p[0] = h; p[K] = h; p[2*K] = lo;
}

// --------- pack transposed weights [K][N] -> [Bh|Bh|Bl] ---------------------
__global__ __launch_bounds__(256) void k_packBt(const float* __restrict__ W,
    __nv_bfloat16* __restrict__ Bp, int N, int K)
{
    int idx = blockIdx.x*256 + threadIdx.x;
    if (idx >= N*K) return;
    int n = idx / K, k = idx % K;
    float v = W[(size_t)k*N + n];
    __nv_bfloat16 h, lo; split_bf16(v, h, lo);
    __nv_bfloat16* p = Bp + (size_t)n*3*K + k;
    p[0] = h; p[K] = h; p[2*K] = lo;
}

// ---------------- weight -> plain fp16 ----------------
__global__ __launch_bounds__(256) void k_packW_h(const float* __restrict__ W,
    __half* __restrict__ out, int nElem)
{
    int idx = blockIdx.x*256 + threadIdx.x;
    if (idx < nElem) out[idx] = __float2half(W[idx]);
}

// ---------------- generic HMMA GEMM: C[M][N] (+)= A @ B^T -------------------
// HALF: 0=bf16, 1=fp16.
// EPI: 0 store f32 | 2 +=x+bias | 3 +=x | 5 store x*oscale | 6 store fp16 | 7 gelu+bias->packed bf16
template<int EPI, int HALF>
__global__ __launch_bounds__(256) void hgemm(
    const __nv_bfloat16* __restrict__ A, const __nv_bfloat16* __restrict__ Bm,
    float* __restrict__ C, __nv_bfloat16* __restrict__ Cp,
    const float* __restrict__ bias,
    int Mreal, int N, int K, float oscale)
{
    __shared__ __nv_bfloat16 As[2][128*40];
    __shared__ __nv_bfloat16 Bs[2][128*40];
    const int tid = threadIdx.x;
    const int mBase = blockIdx.x*128, cBase = blockIdx.y*128;
    const __nv_bfloat16* pA = A + (size_t)mBase*K;
    const __nv_bfloat16* pB = Bm + (size_t)cBase*K;
    const int warp = tid>>5, lane = tid&31;
    const int wm = warp&3, wn = warp>>2;
    float acc[2][8][4];
    #pragma unroll
    for (int i=0;i<2;i++)
        #pragma unroll
        for (int j=0;j<8;j++)
            #pragma unroll
            for (int q=0;q<4;q++) acc[i][j][q] = 0.f;

    #define PREFETCH(ck, buf) do { \
        int _k0 = (ck)*32; \
        _Pragma("unroll") \
        for (int _t=0; _t<4; _t++){ \
            int _j = _t*256 + tid; \
            int _jj = _j & 511; \
            int _r = _jj>>2, _seg = _jj&3; \
            const __nv_bfloat16* _src = ((_j < 512) ? pA : pB) + (size_t)_r*K + _k0 + _seg*8; \
            uint32_t _dst = smem_u32(((_j < 512) ? &As[buf][0] : &Bs[buf][0]) + _r*40 + _seg*8); \
            CP_ASYNC16(_dst, _src); \
        } \
        CP_COMMIT(); \
    } while(0)

    const int nck = K >> 5;
    PREFETCH(0, 0);
    for (int ck = 0; ck < nck; ck++){
        if (ck + 1 < nck){ PREFETCH(ck+1, (ck+1)&1); CP_WAIT(1); }
        else             { CP_WAIT(0); }
        __syncthreads();
        const __nv_bfloat16* as = &As[ck&1][0];
        const __nv_bfloat16* bs = &Bs[ck&1][0];
        #pragma unroll
        for (int ks=0; ks<2; ks++){
            const int kc = ks*16;
            uint32_t a[2][4], bfr[8][2];
            #pragma unroll
            for (int mt=0; mt<2; mt++){
                int row = wm*32 + mt*16 + (lane&7) + ((lane>>3)&1)*8;
                int col = kc + (lane>>4)*8;
                LDSM4(a[mt][0], a[mt][1], a[mt][2], a[mt][3], smem_u32(as + row*40 + col));
            }
            #pragma unroll
            for (int p=0; p<4; p++){
                int row = wn*64 + p*16 + (lane>>4)*8 + (lane&7);
                int col = kc + ((lane>>3)&1)*8;
                uint32_t r0,r1,r2,r3;
                LDSM4(r0,r1,r2,r3, smem_u32(bs + row*40 + col));
                bfr[p*2][0]=r0; bfr[p*2][1]=r1; bfr[p*2+1][0]=r2; bfr[p*2+1][1]=r3;
            }
            #pragma unroll
            for (int mt=0; mt<2; mt++)
                #pragma unroll
                for (int nt=0; nt<8; nt++){
                    if (HALF) { MMA_F16(acc[mt][nt], a[mt], bfr[nt]); }
                    else      { MMA_BF16(acc[mt][nt], a[mt], bfr[nt]); }
                }
        }
        __syncthreads();
    }
    #undef PREFETCH

    const int g = lane>>2, tg = lane&3;
    #pragma unroll
    for (int mt=0; mt<2; mt++){
        int rbase = mBase + wm*32 + mt*16 + g;
        #pragma unroll
        for (int half=0; half<2; half++){
            int r = rbase + half*8;
            if (r >= Mreal) continue;
            #pragma unroll
            for (int nt=0; nt<8; nt++){
                int c0 = cBase + wn*64 + nt*8 + tg*2;
                float v0 = acc[mt][nt][half*2], v1 = acc[mt][nt][half*2+1];
                if (EPI == 6){
                    __half* pp = (__half*)Cp + (size_t)r*N + c0;
                    *(__half2*)pp = __floats2half2_rn(v0, v1);
                } else if (EPI == 7){
                    float g0 = geluf(v0 + bias[c0]), g1 = geluf(v1 + bias[c0+1]);
                    __nv_bfloat16 h0,l0,h1,l1;
                    split_bf16(g0,h0,l0); split_bf16(g1,h1,l1);
                    __nv_bfloat16* pp = Cp + (size_t)r*3*N + c0;
                    *(__nv_bfloat162*)(pp)       = __nv_bfloat162{h0,h1};
                    *(__nv_bfloat162*)(pp + N)   = __nv_bfloat162{l0,l1};
                    *(__nv_bfloat162*)(pp + 2*N) = __nv_bfloat162{h0,h1};
                } else {
                    float* cp = &C[(size_t)r*N + c0];
                    if (EPI == 0){
                        *(float2*)cp = make_float2(v0, v1);
                    } else if (EPI == 5){
                        *(float2*)cp = make_float2(v0*oscale, v1*oscale);
                    } else if (EPI == 2){
                        float2 c = *(float2*)cp;
                        *(float2*)cp = make_float2(c.x + v0 + bias[c0], c.y + v1 + bias[c0+1]);
                    } else {
                        float2 c = *(float2*)cp;
                        *(float2*)cp = make_float2(c.x + v0, c.y + v1);
                    }
                }
            }
        }
    }
}

// ---------------- grouped per-node GEMM (agg=g_ff, res=g_q) ----------------
#define SM_GRP ((128*132 + 96*128)*4)
__global__ __launch_bounds__(256) void k_group()
{
    extern __shared__ float sm[];
    float* s_w = sm;
    float* s_a = sm + 128*132;
    const int n = blockIdx.x, tid = threadIdx.x;
    const float* wb = g_pw + (size_t)n*C_ND*C_ND;
    const float* ab = g_ff + (size_t)n*C_BL*C_ND;
    for (int i = tid; i < (C_ND*C_ND)/4; i += 256){
        int e = i<<2, r = e>>7, c = e&127;
        *(float4*)&s_w[r*132+c] = *(const float4*)(wb+e);
    }
    for (int i = tid; i < (C_BL*C_ND)/4; i += 256)
        ((float4*)s_a)[i] = ((const float4*)ab)[i];
    __syncthreads();
    const int ty = tid>>4, tx = tid&15;
    float acc[6][8];
    #pragma unroll
    for (int i=0;i<6;i++)
        #pragma unroll
        for (int j=0;j<8;j++) acc[i][j]=0.f;
    #pragma unroll 4
    for (int k=0;k<C_ND;k++){
        float4 b0 = *(const float4*)&s_w[k*132 + tx*8];
        float4 b1 = *(const float4*)&s_w[k*132 + tx*8+4];
        float bv[8]={b0.x,b0.y,b0.z,b0.w,b1.x,b1.y,b1.z,b1.w};
        #pragma unroll
        for (int i=0;i<6;i++){
            float a = s_a[(ty*6+i)*C_ND + k];
            #pragma unroll
            for (int j=0;j<8;j++) acc[i][j] = fmaf(a, bv[j], acc[i][j]);
        }
    }
    float* ob = g_q + (size_t)n*C_BL*C_ND;
    #pragma unroll
    for (int i=0;i<6;i++){
        #pragma unroll
        for (int jj=0;jj<2;jj++){
            float4 vv = make_float4(acc[i][jj*4],acc[i][jj*4+1],acc[i][jj*4+2],acc[i][jj*4+3]);
            *(float4*)(ob + (ty*6+i)*C_ND + tx*8 + jj*4) = vv;
        }
    }
}

// ---------------- GroupNorm stats ----------------
__global__ __launch_bounds__(256) void k_gnred()
{
    int bl = blockIdx.x>>2, g = blockIdx.x&3;
    int base = bl*C_ND + g*32;
    float s = 0.f, ss = 0.f;
    for (int i = threadIdx.x; i < C_NN*32; i += 256){
        int n = i>>5, o = i&31;
        float v = g_q[(size_t)n*C_BL*C_ND + base + o];
        s += v; ss += v*v;
    }
    __shared__ float r1[256], r2[256];
    r1[threadIdx.x]=s; r2[threadIdx.x]=ss; __syncthreads();
    for (int st=128; st>0; st>>=1){
        if (threadIdx.x < st){ r1[threadIdx.x]+=r1[threadIdx.x+st]; r2[threadIdx.x]+=r2[threadIdx.x+st]; }
        __syncthreads();
    }
    if (threadIdx.x == 0){
        float mean = r1[0]/(C_NN*32.0f);
        float var = r2[0]/(C_NN*32.0f) - mean*mean;
        g_gmu[blockIdx.x] = mean;
        g_grs[blockIdx.x] = rsqrtf(var + 1e-5f);
    }
}

// ---------------- final fused ----------------
__global__ __launch_bounds__(128) void k_final(
    const float* __restrict__ gn_g, const float* __restrict__ gn_b,
    const float* __restrict__ p2_w, const float* __restrict__ p2_b,
    const float* __restrict__ p1_w, const float* __restrict__ p1_b,
    float* __restrict__ out)
{
    int bn = blockIdx.x, b = bn / C_NN, n = bn % C_NN;
    int lane = threadIdx.x & 31, warp = threadIdx.x >> 5;
    __shared__ float s_s[C_NL];
    int d0 = lane*4, g = d0 >> 5;
    float4 gg = *(const float4*)(gn_g + d0);
    float4 gb = *(const float4*)(gn_b + d0);
    float4 pw = *(const float4*)(p2_w + d0);
    float p2b = p2_b[0];
    for (int l = warp; l < C_NL; l += 4){
        int bl = b*C_NL + l;
        float mu = g_gmu[bl*4 + g], rs = g_grs[bl*4 + g];
        float4 x = *(const float4*)(g_q + (size_t)n*C_BL*C_ND + bl*C_ND + d0);
        float dot = ((x.x-mu)*rs*gg.x+gb.x)*pw.x + ((x.y-mu)*rs*gg.y+gb.y)*pw.y
                  + ((x.z-mu)*rs*gg.z+gb.z)*pw.z + ((x.w-mu)*rs*gg.w+gb.w)*pw.w;
        #pragma unroll
        for (int o=16;o;o>>=1) dot += __shfl_xor_sync(~0u, dot, o);
        if (lane == 0){
            float sv = dot + p2b;
            s_s[l] = sv / (1.f + expf(-sv));
        }
    }
    __syncthreads();
    if (threadIdx.x < C_NLOUT){
        float acc = p1_b[threadIdx.x];
        #pragma unroll
        for (int l=0;l<C_NL;l++) acc = fmaf(p1_w[threadIdx.x*C_NL + l], s_s[l], acc);
        out[(size_t)b*C_NLOUT*C_NN + threadIdx.x*C_NN + n] = acc + g_mean[bn];
    }
}

// ---------------- driver ----------------
extern "C" void kernel_launch(void* const* d_in, const int* in_sizes, int n_in,
                              void* d_out, int out_size)
{
    const float* x_enc = (const float*)d_in[0];
    const float* adj   = (const float*)d_in[1];
    const float* pe_raw= (const float*)d_in[2];
    const float* conv_w= (const float*)d_in[3];
    const float* pos_w = (const float*)d_in[4];
    const float* pos_b = (const float*)d_in[5];
    const float* wq    = (const float*)d_in[6];
    const float* wk    = (const float*)d_in[7];
    const float* wv    = (const float*)d_in[8];
    const float* wo    = (const float*)d_in[9];
    const float* ln1_g = (const float*)d_in[10];
    const float* ln1_b = (const float*)d_in[11];
    const float* ff_w1 = (const float*)d_in[12];
    const float* ff_b1 = (const float*)d_in[13];
    const float* ff_w2 = (const float*)d_in[14];
    const float* ff_b2 = (const float*)d_in[15];
    const float* ln2_g = (const float*)d_in[16];
    const float* ln2_b = (const float*)d_in[17];
    const float* wpool = (const float*)d_in[18];
    const float* gn_g  = (const float*)d_in[19];
    const float* gn_b  = (const float*)d_in[20];
    const float* p2_w  = (const float*)d_in[21];
    const float* p2_b  = (const float*)d_in[22];
    const float* p1_w  = (const float*)d_in[23];
    const float* p1_b  = (const float*)d_in[24];
    float* out = (float*)d_out;

    cudaFuncSetAttribute(k_attn,  cudaFuncAttributeMaxDynamicSharedMemorySize, SM_ATTN);
    cudaFuncSetAttribute(k_group, cudaFuncAttributeMaxDynamicSharedMemorySize, SM_GRP);

    float *penc, *pq, *pff, *ppe, *ppe2, *ppw;
    __nv_bfloat16 *pa2, *pb2, *pap, *pbp;
    cudaGetSymbolAddress((void**)&penc,  g_enc);
    cudaGetSymbolAddress((void**)&pq,    g_q);
    cudaGetSymbolAddress((void**)&pff,   g_ff);
    cudaGetSymbolAddress((void**)&ppe,   g_pe);
    cudaGetSymbolAddress((void**)&ppe2,  g_pe2);
    cudaGetSymbolAddress((void**)&ppw,   g_pw);
    cudaGetSymbolAddress((void**)&pa2,   g_a2);
    cudaGetSymbolAddress((void**)&pb2,   g_b2);
    cudaGetSymbolAddress((void**)&pap,   g_ap);
    cudaGetSymbolAddress((void**)&pbp,   g_bp);

    float* pagg = pff;               // spatial agg aliases g_ff
    __half* pap16 = (__half*)pap;
    __half* pbp16 = (__half*)pbp;
    __half* pqkv  = (__half*)pb2;    // qkv fp16 aliases g_b2

    k_embed<<<C_BN, 128>>>(x_enc, conv_w);
    k_pe<<<(C_NN*C_ND + 255)/256, 256>>>(pe_raw, pos_w, pos_b);
    k_split_adj_h<<<(int)(((size_t)MPAD*KPAD + 255)/256), 256>>>(adj);

    // LN1 -> fp16; fused q/k/v projection (fp16, K=128, N=384) -> qkv in g_b2
    k_ln_h<<<C_ROWS/8, 256>>>(penc, ln1_g, ln1_b, pap16);
    dim3 gP(C_ROWS/128, 1);
    k_packW_h<<<(128*128+255)/256, 256>>>(wq, pbp16,             128*128);
    k_packW_h<<<(128*128+255)/256, 256>>>(wk, pbp16 + 128*128,   128*128);
    k_packW_h<<<(128*128+255)/256, 256>>>(wv, pbp16 + 2*128*128, 128*128);
    hgemm<6,1><<<dim3(C_ROWS/128, 3), 256>>>(pap, pbp, nullptr, pb2, nullptr, C_ROWS, 384, 128, 1.f);

    // fused softmaxes + HMMA attention core -> fp16 att0 in g_ap
    k_attn<<<C_BN, 256, SM_ATTN>>>(pqkv);

    // enc += att0 @ wo^T (fp16, K=128)
    k_packW_h<<<(128*128+255)/256, 256>>>(wo, pbp16, 128*128);
    hgemm<3,1><<<gP, 256>>>(pap, pbp, penc, nullptr, nullptr, C_ROWS, 128, 128, 1.f);

    // FF block (protected): LN2 -> packed bf16; FF1 split-K3 gelu -> packed; FF2 split-K3
    k_ln_pack<<<C_ROWS/8, 256>>>(penc, ln2_g, ln2_b, pap);
    k_packB<<<(512*128+255)/256, 256>>>(ff_w1, pbp, 512, 128);
    hgemm<7,0><<<dim3(C_ROWS/128, 4), 256>>>(pap, pbp, nullptr, pb2, ff_b1, C_ROWS, 512, 384, 1.f);
    k_packB<<<(128*512+255)/256, 256>>>(ff_w2, pbp, 128, 512);
    hgemm<2,0><<<gP, 256>>>(pb2, pbp, penc, nullptr, ff_b2, C_ROWS, 128, 1536, 1.f);

    // spatial: agg = adj @ nf  (plain fp16, scaled)
    k_bt_h<<<dim3(KPAD/32, C_ND/32, C_BL), 256>>>(pb2);
    hgemm<5,1><<<dim3(MPAD/128, NCOL/128), 256>>>(pa2, pb2, pagg, nullptr, nullptr,
                                                  C_NN, NCOL, KPAD, 1.f/1024.f);

    // pe2 = adj @ pe (fp32); pw = pe2 @ wpool (bf16 split-K3, protected)
    sgemm_nn<<<dim3(24, 1), 256>>>(adj, ppe, ppe2, C_NN, 128, C_NN);
    k_packA<<<(int)(((size_t)MPAD*128 + 255)/256), 256>>>(ppe2, pap, C_NN, 128, MPAD);
    k_packBt<<<(16384*128+255)/256, 256>>>(wpool, pbp, 16384, 128);
    hgemm<0,0><<<dim3(MPAD/128, 128), 256>>>(pap, pbp, ppw, nullptr, nullptr, C_NN, 16384, 384, 1.f);

    k_group<<<C_NN, 256, SM_GRP>>>();
    k_gnred<<<C_BL*4, 256>>>();
    k_final<<<C_BN, 128>>>(gn_g, gn_b, p2_w, p2_b, p1_w, p1_b, out);
}

// round 16
// speedup vs baseline: 1.6102x; 1.1095x over previous
#include <cuda_runtime.h>
#include <cuda_bf16.h>
#include <cuda_fp16.h>
#include <math.h>
#include <stdint.h>

#define C_NB 2
#define C_NL 48
#define C_NN 3000
#define C_ND 128
#define C_NLOUT 24
#define C_BN (C_NB*C_NN)
#define C_ROWS (C_BN*C_NL)
#define C_BL (C_NB*C_NL)
#define KPAD 3008
#define MPAD 3072
#define NCOL (C_BL*C_ND)   // 12288

// ---------------- device-global scratch (aliased) ----------------
__device__ float g_mean[C_BN];
__device__ float g_enc [C_ROWS*C_ND];
__device__ float g_q   [C_ROWS*C_ND];          // fp32 res (spatial output)
__device__ float g_ff  [C_ROWS*512];           // also: fp16 agg
__device__ float g_pe  [C_NN*C_ND];
__device__ float g_pe2 [C_NN*C_ND];
__device__ float g_pw  [(size_t)C_NN*C_ND*C_ND];   // fp16 pw lives here
__device__ float g_gmu [C_BL*4];
__device__ float g_grs [C_BL*4];
__device__ __nv_bfloat16 g_a2 [(size_t)MPAD*KPAD];     // fp16 bits (adj*1024)
__device__ __nv_bfloat16 g_b2 [(size_t)C_ROWS*1536];   // qkv fp16 / FF1 packed / nf^T fp16
__device__ __nv_bfloat16 g_ap [(size_t)C_ROWS*384];    // LN outs / att0 / packed pe2
__device__ __nv_bfloat16 g_bp [(size_t)16384*384];     // packed weights

__device__ __forceinline__ float geluf(float x){
    return 0.5f*x*(1.0f+erff(x*0.70710678118654752f));
}
__device__ __forceinline__ uint32_t smem_u32(const void* p){
    uint32_t a;
    asm("{ .reg .u64 t; cvta.to.shared.u64 t, %1; cvt.u32.u64 %0, t; }" : "=r"(a) : "l"(p));
    return a;
}
__device__ __forceinline__ void split_bf16(float v, __nv_bfloat16& h, __nv_bfloat16& lo){
    h = __float2bfloat16(v);
    lo = __float2bfloat16(v - __bfloat162float(h));
}
#define CP_ASYNC16(dst, src) asm volatile("cp.async.cg.shared.global [%0], [%1], 16;" :: "r"(dst), "l"(src))
#define CP_COMMIT() asm volatile("cp.async.commit_group;" ::: "memory")
#define CP_WAIT(n)  asm volatile("cp.async.wait_group %0;" :: "n"(n) : "memory")
#define LDSM4(r0,r1,r2,r3,addr) \
    asm volatile("ldmatrix.sync.aligned.m8n8.x4.shared.b16 {%0,%1,%2,%3}, [%4];" \
        : "=r"(r0),"=r"(r1),"=r"(r2),"=r"(r3) : "r"(addr))
#define LDSM4T(r0,r1,r2,r3,addr) \
    asm volatile("ldmatrix.sync.aligned.m8n8.x4.trans.shared.b16 {%0,%1,%2,%3}, [%4];" \
        : "=r"(r0),"=r"(r1),"=r"(r2),"=r"(r3) : "r"(addr))
#define MMA_BF16(d, a, b) asm volatile( \
    "mma.sync.aligned.m16n8k16.row.col.f32.bf16.bf16.f32 " \
    "{%0,%1,%2,%3}, {%4,%5,%6,%7}, {%8,%9}, {%0,%1,%2,%3};" \
    : "+f"((d)[0]),"+f"((d)[1]),"+f"((d)[2]),"+f"((d)[3]) \
    : "r"((a)[0]),"r"((a)[1]),"r"((a)[2]),"r"((a)[3]), "r"((b)[0]),"r"((b)[1]))
#define MMA_F16(d, a, b) asm volatile( \
    "mma.sync.aligned.m16n8k16.row.col.f32.f16.f16.f32 " \
    "{%0,%1,%2,%3}, {%4,%5,%6,%7}, {%8,%9}, {%0,%1,%2,%3};" \
    : "+f"((d)[0]),"+f"((d)[1]),"+f"((d)[2]),"+f"((d)[3]) \
    : "r"((a)[0]),"r"((a)[1]),"r"((a)[2]),"r"((a)[3]), "r"((b)[0]),"r"((b)[1]))

// ---------------- K1: mean + circular conv1d embedding ----------------
__global__ __launch_bounds__(128) void k_embed(const float* __restrict__ x_enc,
                                               const float* __restrict__ conv_w)
{
    int bn = blockIdx.x, b = bn / C_NN, n = bn % C_NN, t = threadIdx.x;
    __shared__ float red[128];
    __shared__ float xs[C_NL+2];
    float v = 0.f;
    if (t < C_NL) v = x_enc[(size_t)(b*C_NL + t)*C_NN + n];
    red[t] = v; __syncthreads();
    #pragma unroll
    for (int s = 64; s > 0; s >>= 1) { if (t < s) red[t] += red[t+s]; __syncthreads(); }
    float mean = red[0] * (1.f/C_NL);
    if (t == 0) g_mean[bn] = mean;
    if (t < C_NL) xs[t+1] = v - mean;
    __syncthreads();
    if (t == 0) { xs[0] = xs[C_NL]; xs[C_NL+1] = xs[1]; }
    __syncthreads();
    float w0 = conv_w[t*3], w1 = conv_w[t*3+1], w2 = conv_w[t*3+2];
    float* out = g_enc + (size_t)bn*C_NL*C_ND;
    #pragma unroll 4
    for (int l = 0; l < C_NL; l++)
        out[l*C_ND + t] = w0*xs[l] + w1*xs[l+1] + w2*xs[l+2];
}

// ---------------- pe projection ----------------
__global__ __launch_bounds__(256) void k_pe(const float* __restrict__ pe_raw,
    const float* __restrict__ pos_w, const float* __restrict__ pos_b)
{
    int idx = blockIdx.x*256 + threadIdx.x;
    if (idx >= C_NN*C_ND) return;
    int n = idx >> 7, d = idx & 127;
    g_pe[idx] = pe_raw[n]*pos_w[d*3] + pe_raw[C_NN+n]*pos_w[d*3+1]
              + pe_raw[2*C_NN+n]*pos_w[d*3+2] + pos_b[d];
}

// ---------------- LayerNorm -> fp16 row ----------------
__global__ __launch_bounds__(256) void k_ln_h(const float* __restrict__ in,
    const float* __restrict__ ga, const float* __restrict__ be,
    __half* __restrict__ outp)
{
    int row = blockIdx.x*8 + (threadIdx.x>>5), lane = threadIdx.x & 31;
    float4 x = *(const float4*)(in + (size_t)row*C_ND + lane*4);
    float s = x.x+x.y+x.z+x.w;
    #pragma unroll
    for (int o=16;o;o>>=1) s += __shfl_xor_sync(~0u, s, o);
    float mean = s*(1.f/128.f);
    float dx=x.x-mean, dy=x.y-mean, dz=x.z-mean, dw=x.w-mean;
    float sq = dx*dx+dy*dy+dz*dz+dw*dw;
    #pragma unroll
    for (int o=16;o;o>>=1) sq += __shfl_xor_sync(~0u, sq, o);
    float rstd = rsqrtf(sq*(1.f/128.f) + 1e-5f);
    float4 g = *(const float4*)(ga + lane*4), bb = *(const float4*)(be + lane*4);
    __half* p = outp + (size_t)row*C_ND + lane*4;
    *(__half2*)(p)   = __floats2half2_rn(dx*rstd*g.x+bb.x, dy*rstd*g.y+bb.y);
    *(__half2*)(p+2) = __floats2half2_rn(dz*rstd*g.z+bb.z, dw*rstd*g.w+bb.w);
}

// ---------------- LayerNorm -> packed bf16 [h|lo|h] ----------------
__global__ __launch_bounds__(256) void k_ln_pack(const float* __restrict__ in,
    const float* __restrict__ ga, const float* __restrict__ be,
    __nv_bfloat16* __restrict__ outp)
{
    int row = blockIdx.x*8 + (threadIdx.x>>5), lane = threadIdx.x & 31;
    float4 x = *(const float4*)(in + (size_t)row*C_ND + lane*4);
    float s = x.x+x.y+x.z+x.w;
    #pragma unroll
    for (int o=16;o;o>>=1) s += __shfl_xor_sync(~0u, s, o);
    float mean = s*(1.f/128.f);
    float dx=x.x-mean, dy=x.y-mean, dz=x.z-mean, dw=x.w-mean;
    float sq = dx*dx+dy*dy+dz*dz+dw*dw;
    #pragma unroll
    for (int o=16;o;o>>=1) sq += __shfl_xor_sync(~0u, sq, o);
    float rstd = rsqrtf(sq*(1.f/128.f) + 1e-5f);
    float4 g = *(const float4*)(ga + lane*4), bb = *(const float4*)(be + lane*4);
    float vv[4] = { dx*rstd*g.x+bb.x, dy*rstd*g.y+bb.y, dz*rstd*g.z+bb.z, dw*rstd*g.w+bb.w };
    __nv_bfloat16 h[4], lo[4];
    #pragma unroll
    for (int i=0;i<4;i++) split_bf16(vv[i], h[i], lo[i]);
    __nv_bfloat16* p = outp + (size_t)row*384 + lane*4;
    *(__nv_bfloat162*)(p)     = __nv_bfloat162{h[0],h[1]};
    *(__nv_bfloat162*)(p+2)   = __nv_bfloat162{h[2],h[3]};
    *(__nv_bfloat162*)(p+128) = __nv_bfloat162{lo[0],lo[1]};
    *(__nv_bfloat162*)(p+130) = __nv_bfloat162{lo[2],lo[3]};
    *(__nv_bfloat162*)(p+256) = __nv_bfloat162{h[0],h[1]};
    *(__nv_bfloat162*)(p+258) = __nv_bfloat162{h[2],h[3]};
}

// ---------------- tiled fp32 SGEMM (pe2 only) ----------------
#define TBK 16
#define SP 132
__global__ __launch_bounds__(256) void sgemm_nn(
    const float* __restrict__ A, const float* __restrict__ Bm,
    float* __restrict__ C, int M, int N, int K)
{
    __shared__ float As[TBK*SP];
    __shared__ float Bs[TBK*SP];
    const int tid = threadIdx.x, ty = tid>>4, tx = tid&15;
    const int rowBase = blockIdx.x*128, colBase = blockIdx.y*128;
    float acc[8][8];
    #pragma unroll
    for (int i=0;i<8;i++)
        #pragma unroll
        for (int j=0;j<8;j++) acc[i][j]=0.f;
    const int ar = tid>>2, ac = (tid&3)<<2;
    const int numT = (K+TBK-1)/TBK;
    for (int kt=0; kt<numT; kt++){
        const int k0 = kt*TBK;
        #pragma unroll
        for (int hh=0; hh<2; hh++){
            int row = rowBase + ar + hh*64, kg = k0 + ac;
            float4 av = make_float4(0,0,0,0);
            if (row < M){
                const float* ap = A + (size_t)row*K + kg;
                if (kg+3 < K) av = *(const float4*)ap;
                else { if(kg<K)av.x=ap[0]; if(kg+1<K)av.y=ap[1]; if(kg+2<K)av.z=ap[2]; }
            }
            As[(ac+0)*SP+ar+hh*64]=av.x; As[(ac+1)*SP+ar+hh*64]=av.y;
            As[(ac+2)*SP+ar+hh*64]=av.z; As[(ac+3)*SP+ar+hh*64]=av.w;
        }
        #pragma unroll
        for (int hh=0; hh<2; hh++){
            int kr = (tid>>5) + hh*8, c4 = (tid&31)<<2, kg = k0+kr;
            float4 bv = make_float4(0,0,0,0);
            if (kg < K) bv = *(const float4*)(Bm + (size_t)kg*N + colBase + c4);
            *(float4*)&Bs[kr*SP + c4] = bv;
        }
        __syncthreads();
        #pragma unroll
        for (int kk=0; kk<TBK; kk++){
            float4 a0 = *(const float4*)&As[kk*SP + ty*8];
            float4 a1 = *(const float4*)&As[kk*SP + ty*8 + 4];
            float4 b0 = *(const float4*)&Bs[kk*SP + tx*8];
            float4 b1 = *(const float4*)&Bs[kk*SP + tx*8 + 4];
            float av[8]={a0.x,a0.y,a0.z,a0.w,a1.x,a1.y,a1.z,a1.w};
            float bv[8]={b0.x,b0.y,b0.z,b0.w,b1.x,b1.y,b1.z,b1.w};
            #pragma unroll
            for (int i=0;i<8;i++)
                #pragma unroll
                for (int j=0;j<8;j++) acc[i][j] = fmaf(av[i], bv[j], acc[i][j]);
        }
        __syncthreads();
    }
    #pragma unroll
    for (int i=0;i<8;i++){
        int row = rowBase + ty*8 + i;
        if (row >= M) continue;
        float* cp = C + (size_t)row*N + colBase + tx*8;
        #pragma unroll
        for (int jj=0; jj<2; jj++)
            *(float4*)(cp+jj*4) = make_float4(acc[i][jj*4],acc[i][jj*4+1],acc[i][jj*4+2],acc[i][jj*4+3]);
    }
}

// ---- fused attention over qkv[row][384]: softmaxes + ctx + att0 (HMMA fp16)
#define AP 136
#define SM_ATTN ((3*48*AP + 128*AP)*2)
__global__ __launch_bounds__(256) void k_attn(const __half* __restrict__ qkv)
{
    extern __shared__ __half sma[];
    __half* s_q = sma;
    __half* s_k = sma + 48*AP;
    __half* s_v = sma + 2*48*AP;
    __half* s_c = sma + 3*48*AP;
    const int bn = blockIdx.x, tid = threadIdx.x;
    const int warp = tid>>5, lane = tid&31;
    const __half* base = qkv + (size_t)bn*C_NL*384;
    for (int i = tid; i < 3*768; i += 256){
        int t = i/768, j = i%768, row = j>>4, c8 = j&15;
        __half* dst = (t==0? s_q : t==1? s_k : s_v) + row*AP + c8*8;
        const __half* src = base + row*384 + t*128 + c8*8;
        *(uint4*)dst = *(const uint4*)src;
    }
    __syncthreads();
    for (int r = 0; r < 6; r++){
        int row = warp*6 + r;
        float v4[4];
        __half* p = s_q + row*AP + lane*4;
        #pragma unroll
        for (int i=0;i<4;i++) v4[i] = __half2float(p[i]);
        float m = fmaxf(fmaxf(v4[0],v4[1]), fmaxf(v4[2],v4[3]));
        #pragma unroll
        for (int o=16;o;o>>=1) m = fmaxf(m, __shfl_xor_sync(~0u, m, o));
        float e[4], s = 0.f;
        #pragma unroll
        for (int i=0;i<4;i++){ e[i] = expf(v4[i]-m); s += e[i]; }
        #pragma unroll
        for (int o=16;o;o>>=1) s += __shfl_xor_sync(~0u, s, o);
        float sc = 0.08838834764831845f / s;
        *(__half2*)(p)   = __floats2half2_rn(e[0]*sc, e[1]*sc);
        *(__half2*)(p+2) = __floats2half2_rn(e[2]*sc, e[3]*sc);
    }
    if (tid < 128){
        int c = tid;
        float v[C_NL], m = -1e30f;
        #pragma unroll
        for (int l=0;l<C_NL;l++){ v[l] = __half2float(s_k[l*AP + c]); m = fmaxf(m, v[l]); }
        float s = 0.f;
        #pragma unroll
        for (int l=0;l<C_NL;l++){ v[l] = expf(v[l]-m); s += v[l]; }
        float inv = 1.f/s;
        #pragma unroll
        for (int l=0;l<C_NL;l++) s_k[l*AP + c] = __float2half(v[l]*inv);
    }
    __syncthreads();
    {
        const int wm = warp&3, wn = warp>>2;
        float acc[2][8][4];
        #pragma unroll
        for (int i=0;i<2;i++)
            #pragma unroll
            for (int j=0;j<8;j++)
                #pragma unroll
                for (int q=0;q<4;q++) acc[i][j][q]=0.f;
        #pragma unroll
        for (int ks=0; ks<3; ks++){
            const int kc = ks*16;
            uint32_t a[2][4], bfr[8][2];
            #pragma unroll
            for (int mt=0; mt<2; mt++){
                int m0 = wm*32 + mt*16;
                int row = kc + (lane>>4)*8 + (lane&7);
                int col = m0 + ((lane>>3)&1)*8;
                LDSM4T(a[mt][0],a[mt][1],a[mt][2],a[mt][3], smem_u32(s_k + row*AP + col));
            }
            #pragma unroll
            for (int p=0; p<4; p++){
                int n0 = wn*64 + p*16;
                int row = kc + ((lane>>3)&1)*8 + (lane&7);
                int col = n0 + (lane>>4)*8;
                uint32_t r0,r1,r2,r3;
                LDSM4T(r0,r1,r2,r3, smem_u32(s_v + row*AP + col));
                bfr[p*2][0]=r0; bfr[p*2][1]=r1; bfr[p*2+1][0]=r2; bfr[p*2+1][1]=r3;
            }
            #pragma unroll
            for (int mt=0; mt<2; mt++)
                #pragma unroll
                for (int nt=0; nt<8; nt++)
                    MMA_F16(acc[mt][nt], a[mt], bfr[nt]);
        }
        const int g = lane>>2, tg = lane&3;
        #pragma unroll
        for (int mt=0; mt<2; mt++){
            int r0 = wm*32 + mt*16 + g;
            #pragma unroll
            for (int nt=0; nt<8; nt++){
                int c0 = wn*64 + nt*8 + tg*2;
                *(__half2*)(s_c + r0*AP + c0)     = __floats2half2_rn(acc[mt][nt][0], acc[mt][nt][1]);
                *(__half2*)(s_c + (r0+8)*AP + c0) = __floats2half2_rn(acc[mt][nt][2], acc[mt][nt][3]);
            }
        }
    }
    __syncthreads();
    if (warp < 6){
        const int wm = warp>>1, wn = warp&1;
        const int m0 = wm*16;
        float acc[8][4];
        #pragma unroll
        for (int j=0;j<8;j++)
            #pragma unroll
            for (int q=0;q<4;q++) acc[j][q]=0.f;
        #pragma unroll
        for (int ks=0; ks<8; ks++){
            const int kc = ks*16;
            uint32_t a[4], bfr[8][2];
            {
                int row = m0 + (lane&7) + ((lane>>3)&1)*8;
                int col = kc + (lane>>4)*8;
                LDSM4(a[0],a[1],a[2],a[3], smem_u32(s_q + row*AP + col));
            }
            #pragma unroll
            for (int p=0; p<4; p++){
                int n0 = wn*64 + p*16;
                int row = kc + ((lane>>3)&1)*8 + (lane&7);
                int col = n0 + (lane>>4)*8;
                uint32_t r0,r1,r2,r3;
                LDSM4T(r0,r1,r2,r3, smem_u32(s_c + row*AP + col));
                bfr[p*2][0]=r0; bfr[p*2][1]=r1; bfr[p*2+1][0]=r2; bfr[p*2+1][1]=r3;
            }
            #pragma unroll
            for (int nt=0; nt<8; nt++)
                MMA_F16(acc[nt], a, bfr[nt]);
        }
        const int g = lane>>2, tg = lane&3;
        __half* ob = (__half*)g_ap + (size_t)bn*C_NL*C_ND;
        #pragma unroll
        for (int nt=0; nt<8; nt++){
            int c0 = wn*64 + nt*8 + tg*2;
            *(__half2*)(ob + (m0+g)*C_ND + c0)   = __floats2half2_rn(acc[nt][0], acc[nt][1]);
            *(__half2*)(ob + (m0+g+8)*C_ND + c0) = __floats2half2_rn(acc[nt][2], acc[nt][3]);
        }
    }
}

// ---------------- adj -> fp16 (scaled 1024) ----------------
__global__ __launch_bounds__(256) void k_split_adj_h(const float* __restrict__ adj)
{
    size_t idx = (size_t)blockIdx.x*256 + threadIdx.x;
    if (idx >= (size_t)MPAD*KPAD) return;
    int m = (int)(idx / KPAD), k = (int)(idx % KPAD);
    float v = (m < C_NN && k < C_NN) ? adj[(size_t)m*C_NN + k] * 1024.f : 0.f;
    ((__half*)g_a2)[idx] = __float2half(v);
}

// -------- build nf^T fp16 --------------------
__global__ __launch_bounds__(256) void k_bt_h(__nv_bfloat16* __restrict__ B2)
{
    __shared__ float sm[32][33];
    int n0 = blockIdx.x*32, d0 = blockIdx.y*32, bl = blockIdx.z;
    int b = bl / C_NL, l = bl % C_NL;
    int tx = threadIdx.x & 31, ty = threadIdx.x >> 5;
    #pragma unroll
    for (int s=0;s<4;s++){
        int n = n0 + ty + s*8;
        float v = 0.f;
        if (n < C_NN) v = g_enc[((size_t)(b*C_NN + n)*C_NL + l)*C_ND + d0 + tx];
        sm[ty+s*8][tx] = v;
    }
    __syncthreads();
    #pragma unroll
    for (int s=0;s<4;s++){
        int dl = ty + s*8;
        ((__half*)B2)[(size_t)(bl*C_ND + d0 + dl)*KPAD + n0 + tx] = __float2half(sm[tx][dl]);
    }
}

// ---------------- pack fp32 -> [Ah|Al|Ah] bf16 ----------------
__global__ __launch_bounds__(256) void k_packA(const float* __restrict__ A,
    __nv_bfloat16* __restrict__ Ap, int M, int K, int Mpad)
{
    size_t idx = (size_t)blockIdx.x*256 + threadIdx.x;
    if (idx >= (size_t)Mpad*K) return;
    int row = (int)(idx / K), k = (int)(idx % K);
    float v = (row < M) ? A[(size_t)row*K + k] : 0.f;
    __nv_bfloat16 h, lo; split_bf16(v, h, lo);
    __nv_bfloat16* p = Ap + (size_t)row*3*K + k;
    p[0] = h; p[K] = lo; p[2*K] = h;
}

// ---------------- pack weights [N][K] -> [Bh|Bh|Bl] ----------------
__global__ __launch_bounds__(256) void k_packB(const float* __restrict__ B,
    __nv_bfloat16* __restrict__ Bp, int N, int K)
{
    int idx = blockIdx.x*256 + threadIdx.x;
    if (idx >= N*K) return;
    int n = idx / K, k = idx % K;
    float v = B[(size_t)n*K + k];
    __nv_bfloat16 h, lo; split_bf16(v, h, lo);
    __nv_bfloat16* p = Bp + (size_t)n*3*K + k;
    p[0] = h; p[K] = h; p[2*K] = lo;
}

// --------- pack transposed weights [K][N] -> [Bh|Bh|Bl] ---------------------
__global__ __launch_bounds__(256) void k_packBt(const float* __restrict__ W,
    __nv_bfloat16* __restrict__ Bp, int N, int K)
{
    int idx = blockIdx.x*256 + threadIdx.x;
    if (idx >= N*K) return;
    int n = idx / K, k = idx % K;
    float v = W[(size_t)k*N + n];
    __nv_bfloat16 h, lo; split_bf16(v, h, lo);
    __nv_bfloat16* p = Bp + (size_t)n*3*K + k;
    p[0] = h; p[K] = h; p[2*K] = lo;
}

// ---------------- weight -> plain fp16 ----------------
__global__ __launch_bounds__(256) void k_packW_h(const float* __restrict__ W,
    __half* __restrict__ out, int nElem)
{
    int idx = blockIdx.x*256 + threadIdx.x;
    if (idx < nElem) out[idx] = __float2half(W[idx]);
}

// ---------------- generic HMMA GEMM: C[M][N] (+)= A @ B^T -------------------
// HALF: 0=bf16, 1=fp16.
// EPI: 0 f32 | 2 +=x+bias | 3 +=x | 5 f32 x*oscale | 6 fp16 | 7 gelu+bias->packed bf16 | 8 fp16 x*oscale
template<int EPI, int HALF>
__global__ __launch_bounds__(256) void hgemm(
    const __nv_bfloat16* __restrict__ A, const __nv_bfloat16* __restrict__ Bm,
    float* __restrict__ C, __nv_bfloat16* __restrict__ Cp,
    const float* __restrict__ bias,
    int Mreal, int N, int K, float oscale)
{
    __shared__ __nv_bfloat16 As[2][128*40];
    __shared__ __nv_bfloat16 Bs[2][128*40];
    const int tid = threadIdx.x;
    const int mBase = blockIdx.x*128, cBase = blockIdx.y*128;
    const __nv_bfloat16* pA = A + (size_t)mBase*K;
    const __nv_bfloat16* pB = Bm + (size_t)cBase*K;
    const int warp = tid>>5, lane = tid&31;
    const int wm = warp&3, wn = warp>>2;
    float acc[2][8][4];
    #pragma unroll
    for (int i=0;i<2;i++)
        #pragma unroll
        for (int j=0;j<8;j++)
            #pragma unroll
            for (int q=0;q<4;q++) acc[i][j][q] = 0.f;

    #define PREFETCH(ck, buf) do { \
        int _k0 = (ck)*32; \
        _Pragma("unroll") \
        for (int _t=0; _t<4; _t++){ \
            int _j = _t*256 + tid; \
            int _jj = _j & 511; \
            int _r = _jj>>2, _seg = _jj&3; \
            const __nv_bfloat16* _src = ((_j < 512) ? pA : pB) + (size_t)_r*K + _k0 + _seg*8; \
            uint32_t _dst = smem_u32(((_j < 512) ? &As[buf][0] : &Bs[buf][0]) + _r*40 + _seg*8); \
            CP_ASYNC16(_dst, _src); \
        } \
        CP_COMMIT(); \
    } while(0)

    const int nck = K >> 5;
    PREFETCH(0, 0);
    for (int ck = 0; ck < nck; ck++){
        if (ck + 1 < nck){ PREFETCH(ck+1, (ck+1)&1); CP_WAIT(1); }
        else             { CP_WAIT(0); }
        __syncthreads();
        const __nv_bfloat16* as = &As[ck&1][0];
        const __nv_bfloat16* bs = &Bs[ck&1][0];
        #pragma unroll
        for (int ks=0; ks<2; ks++){
            const int kc = ks*16;
            uint32_t a[2][4], bfr[8][2];
            #pragma unroll
            for (int mt=0; mt<2; mt++){
                int row = wm*32 + mt*16 + (lane&7) + ((lane>>3)&1)*8;
                int col = kc + (lane>>4)*8;
                LDSM4(a[mt][0], a[mt][1], a[mt][2], a[mt][3], smem_u32(as + row*40 + col));
            }
            #pragma unroll
            for (int p=0; p<4; p++){
                int row = wn*64 + p*16 + (lane>>4)*8 + (lane&7);
                int col = kc + ((lane>>3)&1)*8;
                uint32_t r0,r1,r2,r3;
                LDSM4(r0,r1,r2,r3, smem_u32(bs + row*40 + col));
                bfr[p*2][0]=r0; bfr[p*2][1]=r1; bfr[p*2+1][0]=r2; bfr[p*2+1][1]=r3;
            }
            #pragma unroll
            for (int mt=0; mt<2; mt++)
                #pragma unroll
                for (int nt=0; nt<8; nt++){
                    if (HALF) { MMA_F16(acc[mt][nt], a[mt], bfr[nt]); }
                    else      { MMA_BF16(acc[mt][nt], a[mt], bfr[nt]); }
                }
        }
        __syncthreads();
    }
    #undef PREFETCH

    const int g = lane>>2, tg = lane&3;
    #pragma unroll
    for (int mt=0; mt<2; mt++){
        int rbase = mBase + wm*32 + mt*16 + g;
        #pragma unroll
        for (int half=0; half<2; half++){
            int r = rbase + half*8;
            if (r >= Mreal) continue;
            #pragma unroll
            for (int nt=0; nt<8; nt++){
                int c0 = cBase + wn*64 + nt*8 + tg*2;
                float v0 = acc[mt][nt][half*2], v1 = acc[mt][nt][half*2+1];
                if (EPI == 6){
                    __half* pp = (__half*)Cp + (size_t)r*N + c0;
                    *(__half2*)pp = __floats2half2_rn(v0, v1);
                } else if (EPI == 8){
                    __half* pp = (__half*)Cp + (size_t)r*N + c0;
                    *(__half2*)pp = __floats2half2_rn(v0*oscale, v1*oscale);
                } else if (EPI == 7){
                    float g0 = geluf(v0 + bias[c0]), g1 = geluf(v1 + bias[c0+1]);
                    __nv_bfloat16 h0,l0,h1,l1;
                    split_bf16(g0,h0,l0); split_bf16(g1,h1,l1);
                    __nv_bfloat16* pp = Cp + (size_t)r*3*N + c0;
                    *(__nv_bfloat162*)(pp)       = __nv_bfloat162{h0,h1};
                    *(__nv_bfloat162*)(pp + N)   = __nv_bfloat162{l0,l1};
                    *(__nv_bfloat162*)(pp + 2*N) = __nv_bfloat162{h0,h1};
                } else {
                    float* cp = &C[(size_t)r*N + c0];
                    if (EPI == 0){
                        *(float2*)cp = make_float2(v0, v1);
                    } else if (EPI == 5){
                        *(float2*)cp = make_float2(v0*oscale, v1*oscale);
                    } else if (EPI == 2){
                        float2 c = *(float2*)cp;
                        *(float2*)cp = make_float2(c.x + v0 + bias[c0], c.y + v1 + bias[c0+1]);
                    } else {
                        float2 c = *(float2*)cp;
                        *(float2*)cp = make_float2(c.x + v0, c.y + v1);
                    }
                }
            }
        }
    }
}

// ------- grouped per-node GEMM, fp16 HMMA: res[n](96x128) = agg[n] @ pw[n] ----
#define GP 136
#define SM_GRP16 ((128*GP + 96*GP)*2)
__global__ __launch_bounds__(256) void k_group16(const __half* __restrict__ agg,
                                                 const __half* __restrict__ pw)
{
    extern __shared__ __half smg[];
    __half* s_b = smg;            // pw[n]: [K=128][N=128], pitch GP
    __half* s_a = smg + 128*GP;   // agg[n]: [M=96][K=128], pitch GP
    const int n = blockIdx.x, tid = threadIdx.x;
    const int warp = tid>>5, lane = tid&31;
    const __half* pwn = pw + (size_t)n*C_ND*C_ND;
    const __half* agn = agg + (size_t)n*C_BL*C_ND;
    for (int i = tid; i < 2048; i += 256){
        int r = i>>4, c8 = i&15;
        *(uint4*)(s_b + r*GP + c8*8) = *(const uint4*)(pwn + r*128 + c8*8);
    }
    for (int i = tid; i < 1536; i += 256){
        int r = i>>4, c8 = i&15;
        *(uint4*)(s_a + r*GP + c8*8) = *(const uint4*)(agn + r*128 + c8*8);
    }
    __syncthreads();
    if (warp >= 6) return;
    const int wm = warp>>1, wn = warp&1;   // 3m x 2n, warp tile 32x64
    float acc[2][8][4];
    #pragma unroll
    for (int i=0;i<2;i++)
        #pragma unroll
        for (int j=0;j<8;j++)
            #pragma unroll
            for (int q=0;q<4;q++) acc[i][j][q]=0.f;
    #pragma unroll
    for (int ks=0; ks<8; ks++){
        const int kc = ks*16;
        uint32_t a[2][4], bfr[8][2];
        #pragma unroll
        for (int mt=0; mt<2; mt++){
            int row = wm*32 + mt*16 + (lane&7) + ((lane>>3)&1)*8;
            int col = kc + (lane>>4)*8;
            LDSM4(a[mt][0],a[mt][1],a[mt][2],a[mt][3], smem_u32(s_a + row*GP + col));
        }
        #pragma unroll
        for (int p=0; p<4; p++){
            int n0 = wn*64 + p*16;
            int row = kc + ((lane>>3)&1)*8 + (lane&7);
            int col = n0 + (lane>>4)*8;
            uint32_t r0,r1,r2,r3;
            LDSM4T(r0,r1,r2,r3, smem_u32(s_b + row*GP + col));
            bfr[p*2][0]=r0; bfr[p*2][1]=r1; bfr[p*2+1][0]=r2; bfr[p*2+1][1]=r3;
        }
        #pragma unroll
        for (int mt=0; mt<2; mt++)
            #pragma unroll
            for (int nt=0; nt<8; nt++)
                MMA_F16(acc[mt][nt], a[mt], bfr[nt]);
    }
    const int g = lane>>2, tg = lane&3;
    float* ob = g_q + (size_t)n*C_BL*C_ND;
    #pragma unroll
    for (int mt=0; mt<2; mt++){
        int r0 = wm*32 + mt*16 + g;
        #pragma unroll
        for (int nt=0; nt<8; nt++){
            int c0 = wn*64 + nt*8 + tg*2;
            *(float2*)(ob + r0*C_ND + c0)     = make_float2(acc[mt][nt][0], acc[mt][nt][1]);
            *(float2*)(ob + (r0+8)*C_ND + c0) = make_float2(acc[mt][nt][2], acc[mt][nt][3]);
        }
    }
}

// ---------------- GroupNorm stats ----------------
__global__ __launch_bounds__(256) void k_gnred()
{
    int bl = blockIdx.x>>2, g = blockIdx.x&3;
    int base = bl*C_ND + g*32;
    float s = 0.f, ss = 0.f;
    for (int i = threadIdx.x; i < C_NN*32; i += 256){
        int n = i>>5, o = i&31;
        float v = g_q[(size_t)n*C_BL*C_ND + base + o];
        s += v; ss += v*v;
    }
    __shared__ float r1[256], r2[256];
    r1[threadIdx.x]=s; r2[threadIdx.x]=ss; __syncthreads();
    for (int st=128; st>0; st>>=1){
        if (threadIdx.x < st){ r1[threadIdx.x]+=r1[threadIdx.x+st]; r2[threadIdx.x]+=r2[threadIdx.x+st]; }
        __syncthreads();
    }
    if (threadIdx.x == 0){
        float mean = r1[0]/(C_NN*32.0f);
        float var = r2[0]/(C_NN*32.0f) - mean*mean;
        g_gmu[blockIdx.x] = mean;
        g_grs[blockIdx.x] = rsqrtf(var + 1e-5f);
    }
}

// ---------------- final fused ----------------
__global__ __launch_bounds__(128) void k_final(
    const float* __restrict__ gn_g, const float* __restrict__ gn_b,
    const float* __restrict__ p2_w, const float* __restrict__ p2_b,
    const float* __restrict__ p1_w, const float* __restrict__ p1_b,
    float* __restrict__ out)
{
    int bn = blockIdx.x, b = bn / C_NN, n = bn % C_NN;
    int lane = threadIdx.x & 31, warp = threadIdx.x >> 5;
    __shared__ float s_s[C_NL];
    int d0 = lane*4, g = d0 >> 5;
    float4 gg = *(const float4*)(gn_g + d0);
    float4 gb = *(const float4*)(gn_b + d0);
    float4 pw = *(const float4*)(p2_w + d0);
    float p2b = p2_b[0];
    for (int l = warp; l < C_NL; l += 4){
        int bl = b*C_NL + l;
        float mu = g_gmu[bl*4 + g], rs = g_grs[bl*4 + g];
        float4 x = *(const float4*)(g_q + (size_t)n*C_BL*C_ND + bl*C_ND + d0);
        float dot = ((x.x-mu)*rs*gg.x+gb.x)*pw.x + ((x.y-mu)*rs*gg.y+gb.y)*pw.y
                  + ((x.z-mu)*rs*gg.z+gb.z)*pw.z + ((x.w-mu)*rs*gg.w+gb.w)*pw.w;
        #pragma unroll
        for (int o=16;o;o>>=1) dot += __shfl_xor_sync(~0u, dot, o);
        if (lane == 0){
            float sv = dot + p2b;
            s_s[l] = sv / (1.f + expf(-sv));
        }
    }
    __syncthreads();
    if (threadIdx.x < C_NLOUT){
        float acc = p1_b[threadIdx.x];
        #pragma unroll
        for (int l=0;l<C_NL;l++) acc = fmaf(p1_w[threadIdx.x*C_NL + l], s_s[l], acc);
        out[(size_t)b*C_NLOUT*C_NN + threadIdx.x*C_NN + n] = acc + g_mean[bn];
    }
}

// ---------------- driver ----------------
extern "C" void kernel_launch(void* const* d_in, const int* in_sizes, int n_in,
                              void* d_out, int out_size)
{
    const float* x_enc = (const float*)d_in[0];
    const float* adj   = (const float*)d_in[1];
    const float* pe_raw= (const float*)d_in[2];
    const float* conv_w= (const float*)d_in[3];
    const float* pos_w = (const float*)d_in[4];
    const float* pos_b = (const float*)d_in[5];
    const float* wq    = (const float*)d_in[6];
    const float* wk    = (const float*)d_in[7];
    const float* wv    = (const float*)d_in[8];
    const float* wo    = (const float*)d_in[9];
    const float* ln1_g = (const float*)d_in[10];
    const float* ln1_b = (const float*)d_in[11];
    const float* ff_w1 = (const float*)d_in[12];
    const float* ff_b1 = (const float*)d_in[13];
    const float* ff_w2 = (const float*)d_in[14];
    const float* ff_b2 = (const float*)d_in[15];
    const float* ln2_g = (const float*)d_in[16];
    const float* ln2_b = (const float*)d_in[17];
    const float* wpool = (const float*)d_in[18];
    const float* gn_g  = (const float*)d_in[19];
    const float* gn_b  = (const float*)d_in[20];
    const float* p2_w  = (const float*)d_in[21];
    const float* p2_b  = (const float*)d_in[22];
    const float* p1_w  = (const float*)d_in[23];
    const float* p1_b  = (const float*)d_in[24];
    float* out = (float*)d_out;

    cudaFuncSetAttribute(k_attn,    cudaFuncAttributeMaxDynamicSharedMemorySize, SM_ATTN);
    cudaFuncSetAttribute(k_group16, cudaFuncAttributeMaxDynamicSharedMemorySize, SM_GRP16);

    float *penc, *pq, *pff, *ppe, *ppe2, *ppw;
    __nv_bfloat16 *pa2, *pb2, *pap, *pbp;
    cudaGetSymbolAddress((void**)&penc,  g_enc);
    cudaGetSymbolAddress((void**)&pq,    g_q);
    cudaGetSymbolAddress((void**)&pff,   g_ff);
    cudaGetSymbolAddress((void**)&ppe,   g_pe);
    cudaGetSymbolAddress((void**)&ppe2,  g_pe2);
    cudaGetSymbolAddress((void**)&ppw,   g_pw);
    cudaGetSymbolAddress((void**)&pa2,   g_a2);
    cudaGetSymbolAddress((void**)&pb2,   g_b2);
    cudaGetSymbolAddress((void**)&pap,   g_ap);
    cudaGetSymbolAddress((void**)&pbp,   g_bp);

    __half* pagg16 = (__half*)pff;   // fp16 agg aliases g_ff
    __half* ppw16  = (__half*)ppw;   // fp16 pw in g_pw
    __half* pap16  = (__half*)pap;
    __half* pbp16  = (__half*)pbp;
    __half* pqkv   = (__half*)pb2;

    k_embed<<<C_BN, 128>>>(x_enc, conv_w);
    k_pe<<<(C_NN*C_ND + 255)/256, 256>>>(pe_raw, pos_w, pos_b);
    k_split_adj_h<<<(int)(((size_t)MPAD*KPAD + 255)/256), 256>>>(adj);

    // LN1 -> fp16; fused q/k/v projection (fp16, K=128, N=384)
    k_ln_h<<<C_ROWS/8, 256>>>(penc, ln1_g, ln1_b, pap16);
    dim3 gP(C_ROWS/128, 1);
    k_packW_h<<<(128*128+255)/256, 256>>>(wq, pbp16,             128*128);
    k_packW_h<<<(128*128+255)/256, 256>>>(wk, pbp16 + 128*128,   128*128);
    k_packW_h<<<(128*128+255)/256, 256>>>(wv, pbp16 + 2*128*128, 128*128);
    hgemm<6,1><<<dim3(C_ROWS/128, 3), 256>>>(pap, pbp, nullptr, pb2, nullptr, C_ROWS, 384, 128, 1.f);

    k_attn<<<C_BN, 256, SM_ATTN>>>(pqkv);

    // enc += att0 @ wo^T (fp16)
    k_packW_h<<<(128*128+255)/256, 256>>>(wo, pbp16, 128*128);
    hgemm<3,1><<<gP, 256>>>(pap, pbp, penc, nullptr, nullptr, C_ROWS, 128, 128, 1.f);

    // FF block (protected split-K3)
    k_ln_pack<<<C_ROWS/8, 256>>>(penc, ln2_g, ln2_b, pap);
    k_packB<<<(512*128+255)/256, 256>>>(ff_w1, pbp, 512, 128);
    hgemm<7,0><<<dim3(C_ROWS/128, 4), 256>>>(pap, pbp, nullptr, pb2, ff_b1, C_ROWS, 512, 384, 1.f);
    k_packB<<<(128*512+255)/256, 256>>>(ff_w2, pbp, 128, 512);
    hgemm<2,0><<<gP, 256>>>(pb2, pbp, penc, nullptr, ff_b2, C_ROWS, 128, 1536, 1.f);

    // spatial: agg = adj @ nf (fp16 in, fp16 out with rescale)
    k_bt_h<<<dim3(KPAD/32, C_ND/32, C_BL), 256>>>(pb2);
    hgemm<8,1><<<dim3(MPAD/128, NCOL/128), 256>>>(pa2, pb2, nullptr, (__nv_bfloat16*)pagg16, nullptr,
                                                  C_NN, NCOL, KPAD, 1.f/1024.f);

    // pe2 = adj @ pe (fp32); pw = pe2 @ wpool (exact split-K3 compute, fp16 store)
    sgemm_nn<<<dim3(24, 1), 256>>>(adj, ppe, ppe2, C_NN, 128, C_NN);
    k_packA<<<(int)(((size_t)MPAD*128 + 255)/256), 256>>>(ppe2, pap, C_NN, 128, MPAD);
    k_packBt<<<(16384*128+255)/256, 256>>>(wpool, pbp, 16384, 128);
    hgemm<6,0><<<dim3(MPAD/128, 128), 256>>>(pap, pbp, nullptr, (__nv_bfloat16*)ppw16, nullptr,
                                             C_NN, 16384, 384, 1.f);

    k_group16<<<C_NN, 256, SM_GRP16>>>(pagg16, ppw16);
    k_gnred<<<C_BL*4, 256>>>();
    k_final<<<C_BN, 128>>>(gn_g, gn_b, p2_w, p2_b, p1_w, p1_b, out);
}